// round 12
// baseline (speedup 1.0000x reference)
#include <cuda_runtime.h>
#include <cuda_bf16.h>
#include <math.h>
#include <cstdint>

// Problem constants
#define B    64
#define S    1024
#define D    512
#define H    512
#define G    2048      // 4*H
#define WROW 1024      // D+H, row stride of W
#define M_TOT (S*B)    // 65536 GEMM rows, m = t*B + b
#define NCTA 128
#define NTHR 256

// ---------------------------------------------------------------------------
// Scratch (__device__ globals: sanctioned alloc-free workaround)
// ---------------------------------------------------------------------------
__device__ __nv_bfloat16 g_xh [(size_t)M_TOT * 512];     // layer-0 A hi
__device__ __nv_bfloat16 g_xl [(size_t)M_TOT * 512];     // layer-0 A lo
__device__ __nv_bfloat16 g_y1h[(size_t)M_TOT * 512];     // layer-1 A hi
__device__ __nv_bfloat16 g_y1l[(size_t)M_TOT * 512];     // layer-1 A lo
__device__ __nv_bfloat16 g_wh [2 * (size_t)G * WROW];    // W hi, [layer][n][WROW]
__device__ __nv_bfloat16 g_wl [2 * (size_t)G * WROW];    // W lo
__device__ float g_xg[(size_t)S * B * G];                // input gates (t*B+b, G)
__device__ __nv_bfloat16 g_hbf[2][2][B * H];             // ping-pong h, [buf][hi/lo]
__device__ unsigned g_flags[2][NCTA * 32];               // barrier flags, 128B-spaced

// ---------------------------------------------------------------------------
// PTX helpers (arch-portable: sm_80+ only)
// ---------------------------------------------------------------------------
__device__ __forceinline__ uint32_t smem_u32(const void* p) {
    uint32_t a;
    asm("{ .reg .u64 t; cvta.to.shared.u64 t, %1; cvt.u32.u64 %0, t; }"
        : "=r"(a) : "l"(p));
    return a;
}

#define CPASYNC(sm, gm) \
    asm volatile("cp.async.cg.shared.global [%0], [%1], 16;" :: "r"(sm), "l"(gm))
#define CPCOMMIT() asm volatile("cp.async.commit_group;" ::: "memory")
#define CPWAIT(n)  asm volatile("cp.async.wait_group %0;" :: "n"(n) : "memory")

#define LDSM4(r0, r1, r2, r3, addr) \
    asm volatile("ldmatrix.sync.aligned.m8n8.x4.shared.b16 {%0,%1,%2,%3}, [%4];" \
        : "=r"(r0), "=r"(r1), "=r"(r2), "=r"(r3) : "r"(addr))
#define LDSM2(r0, r1, addr) \
    asm volatile("ldmatrix.sync.aligned.m8n8.x2.shared.b16 {%0,%1}, [%2];" \
        : "=r"(r0), "=r"(r1) : "r"(addr))

#define MMA16816(d, a, b) \
    asm volatile("mma.sync.aligned.m16n8k16.row.col.f32.bf16.bf16.f32 " \
        "{%0,%1,%2,%3},{%4,%5,%6,%7},{%8,%9},{%0,%1,%2,%3};" \
        : "+f"((d)[0]), "+f"((d)[1]), "+f"((d)[2]), "+f"((d)[3]) \
        : "r"((a)[0]), "r"((a)[1]), "r"((a)[2]), "r"((a)[3]), \
          "r"((b)[0]), "r"((b)[1]))

__device__ __forceinline__ void bsplit(float v, __nv_bfloat16& h, __nv_bfloat16& l) {
    h = __float2bfloat16(v);
    l = __float2bfloat16(v - __bfloat162float(h));
}

// ---------------------------------------------------------------------------
// Split kernels: fp32 -> bf16 hi/lo
// ---------------------------------------------------------------------------
__global__ void __launch_bounds__(256) split_x(const float* __restrict__ x)
{
    const size_t i4 = (size_t)blockIdx.x * 256 + threadIdx.x;  // over M_TOT*512/4
    const float4 v = ((const float4*)x)[i4];
    const size_t idx = i4 * 4;                 // (b, t, k) in x layout
    const int k = (int)(idx & 511);
    const int t = (int)((idx >> 9) & 1023);
    const int b = (int)(idx >> 19);
    const size_t o = ((size_t)t * B + b) * 512 + k;   // GEMM A layout (m, k)
    __nv_bfloat16 h0, l0, h1, l1, h2, l2, h3, l3;
    bsplit(v.x, h0, l0); bsplit(v.y, h1, l1);
    bsplit(v.z, h2, l2); bsplit(v.w, h3, l3);
    __nv_bfloat162 a, bb2;
    a.x = h0; a.y = h1; bb2.x = h2; bb2.y = h3;
    *(__nv_bfloat162*)(g_xh + o)     = a;
    *(__nv_bfloat162*)(g_xh + o + 2) = bb2;
    a.x = l0; a.y = l1; bb2.x = l2; bb2.y = l3;
    *(__nv_bfloat162*)(g_xl + o)     = a;
    *(__nv_bfloat162*)(g_xl + o + 2) = bb2;
}

// Full-W split: source layout [layer][n][WROW] is copied linearly.
__global__ void __launch_bounds__(256) split_w(const float* __restrict__ W)
{
    const size_t i4 = (size_t)blockIdx.x * 256 + threadIdx.x;  // over 2*G*WROW/4
    const float4 v = ((const float4*)W)[i4];
    const size_t idx = i4 * 4;
    __nv_bfloat16 h0, l0, h1, l1, h2, l2, h3, l3;
    bsplit(v.x, h0, l0); bsplit(v.y, h1, l1);
    bsplit(v.z, h2, l2); bsplit(v.w, h3, l3);
    __nv_bfloat162 a, bb2;
    a.x = h0; a.y = h1; bb2.x = h2; bb2.y = h3;
    *(__nv_bfloat162*)(g_wh + idx)     = a;
    *(__nv_bfloat162*)(g_wh + idx + 2) = bb2;
    a.x = l0; a.y = l1; bb2.x = l2; bb2.y = l3;
    *(__nv_bfloat162*)(g_wl + idx)     = a;
    *(__nv_bfloat162*)(g_wl + idx + 2) = bb2;
}

// Convert h0 (fp32) into the bf16 ping-pong buffer read at t=0 (index 1).
__global__ void __launch_bounds__(256) init_h(const float* __restrict__ h0l)
{
    const int i = blockIdx.x * 256 + threadIdx.x;   // 0..B*H-1
    __nv_bfloat16 hh, hl;
    bsplit(h0l[i], hh, hl);
    g_hbf[1][0][i] = hh;
    g_hbf[1][1][i] = hl;
}

// ---------------------------------------------------------------------------
// HMMA bf16-split GEMM: xg[m][n] = sum_k A[m][k]*Wx[n][k] + bias[n]
// (unchanged from R8 — proven; also zeroes this layer's barrier flags)
// ---------------------------------------------------------------------------
#define APITCH 72
#define ATILEB (128 * APITCH * 2)        // 18432 B per operand tile
#define STAGEB (2 * ATILEB)              // A + B per stage
#define GSMEM  (2 * STAGEB)              // double buffered = 73728 B

__global__ void __launch_bounds__(256) gemm_hmma(
    const float* __restrict__ bias, int layer)
{
    if (blockIdx.x == 0 && blockIdx.y == 0 && threadIdx.x < NCTA)
        g_flags[layer][threadIdx.x * 32] = 0u;   // reset barrier flags

    const __nv_bfloat16* __restrict__ Ah = layer ? g_y1h : g_xh;
    const __nv_bfloat16* __restrict__ Al = layer ? g_y1l : g_xl;
    const __nv_bfloat16* __restrict__ Bh = g_wh + (size_t)layer * G * WROW;
    const __nv_bfloat16* __restrict__ Bl = g_wl + (size_t)layer * G * WROW;
    const __nv_bfloat16* APs[3] = { Ah, Ah, Al };
    const __nv_bfloat16* BPs[3] = { Bh, Bl, Bh };

    extern __shared__ char dynsm[];
    const uint32_t sbase = smem_u32(dynsm);
    const int tid = threadIdx.x, lane = tid & 31, warp = tid >> 5;
    const int wm = warp & 1, wn = warp >> 1;          // warp grid 2(M) x 4(N)
    const int m0 = blockIdx.y * 128, n0 = blockIdx.x * 128;

    const int sel = lane >> 3, lr = lane & 7;
    const uint32_t aRow  = wm * 64 + (sel & 1) * 8 + lr;
    const uint32_t aColB = (sel >> 1) * 8;
    const uint32_t bRow  = wn * 32 + lr;
    const uint32_t bColB = (sel & 1) * 8;

    float d[4][4][4];
#pragma unroll
    for (int i = 0; i < 4; i++)
#pragma unroll
        for (int j = 0; j < 4; j++)
#pragma unroll
            for (int q = 0; q < 4; q++) d[i][j][q] = 0.0f;

    auto issue = [&](int c, int buf) {
        const int term = c >> 3, kg = (c & 7) * 64;
        const __nv_bfloat16* Ap = APs[term];
        const __nv_bfloat16* Bp = BPs[term];
        const uint32_t sA = sbase + buf * STAGEB;
        const uint32_t sB = sA + ATILEB;
#pragma unroll
        for (int p = 0; p < 4; p++) {
            const int f = tid + p * 256;
            const int row = f >> 3, seg = f & 7;
            const uint32_t so = (uint32_t)(row * APITCH + seg * 8) * 2;
            CPASYNC(sA + so, Ap + (size_t)(m0 + row) * 512 + kg + seg * 8);
            CPASYNC(sB + so, Bp + (size_t)(n0 + row) * WROW + kg + seg * 8);
        }
        CPCOMMIT();
    };

    issue(0, 0);
    for (int c = 0; c < 24; c++) {
        const int buf = c & 1;
        if (c + 1 < 24) { issue(c + 1, buf ^ 1); CPWAIT(1); }
        else            { CPWAIT(0); }
        __syncthreads();

        const uint32_t sA = sbase + buf * STAGEB;
        const uint32_t sB = sA + ATILEB;
        const uint32_t aBase = sA + (aRow * APITCH + aColB) * 2;
        const uint32_t bBase = sB + (bRow * APITCH + bColB) * 2;

#pragma unroll
        for (int ks = 0; ks < 4; ks++) {
            uint32_t a[4][4], b[4][2];
#pragma unroll
            for (int i = 0; i < 4; i++)
                LDSM4(a[i][0], a[i][1], a[i][2], a[i][3],
                      aBase + (uint32_t)(i * 16 * APITCH + ks * 16) * 2);
#pragma unroll
            for (int j = 0; j < 4; j++)
                LDSM2(b[j][0], b[j][1],
                      bBase + (uint32_t)(j * 8 * APITCH + ks * 16) * 2);
#pragma unroll
            for (int i = 0; i < 4; i++)
#pragma unroll
                for (int j = 0; j < 4; j++)
                    MMA16816(d[i][j], a[i], b[j]);
        }
        __syncthreads();
    }

    const int gq = lane >> 2, tq = lane & 3;
#pragma unroll
    for (int i = 0; i < 4; i++) {
#pragma unroll
        for (int j = 0; j < 4; j++) {
            const int col = n0 + wn * 32 + j * 8 + tq * 2;
            const int row0 = m0 + wm * 64 + i * 16 + gq;
            const float b0 = bias[col], b1 = bias[col + 1];
            float2 v0, v1;
            v0.x = d[i][j][0] + b0; v0.y = d[i][j][1] + b1;
            v1.x = d[i][j][2] + b0; v1.y = d[i][j][3] + b1;
            *(float2*)(g_xg + (size_t)row0 * G + col) = v0;
            *(float2*)(g_xg + (size_t)(row0 + 8) * G + col) = v1;
        }
    }
}

// ---------------------------------------------------------------------------
// Persistent HMMA recurrence, v3:
//  - distributed flag barrier (128 x 128B-spaced flags; no atomic contention)
//  - h stage split into 2 k-chunks; mma on chunk0 overlaps chunk1 in flight
//  - xg via cp.async group waited only before elementwise
// ---------------------------------------------------------------------------
#define HPITCH 520                       // halves per row: 1040 B
#define HS_H   0
#define HS_L   (HS_H + 64 * HPITCH * 2)      // 66560
#define WS_H   (HS_L + 64 * HPITCH * 2)      // 133120
#define WS_L   (WS_H + 16 * HPITCH * 2)      // 149760
#define XS_OFF (WS_L + 16 * HPITCH * 2)      // 166400, [64][16] fp32
#define GR_OFF (XS_OFF + 64 * 16 * 4)        // 170496, [2][64][18] fp32
#define P2_SMEM (GR_OFF + 2 * 64 * 18 * 4)   // 179712 B

__global__ void __launch_bounds__(NTHR, 1) lstm_persist(
    int layer,
    const float* __restrict__ c0l,
    float* __restrict__ dout)
{
    extern __shared__ char dynsm[];
    const uint32_t sb = smem_u32(dynsm);
    const int tid = threadIdx.x, lane = tid & 31, warp = tid >> 5;
    const int wm = warp & 3;            // m-tile: batches [wm*16, wm*16+16)
    const int wk = warp >> 2;           // k-half: k in [wk*256, wk*256+256)
    const int u0 = blockIdx.x * 4;
    unsigned* flags = g_flags[layer];

    // --- Stage Wh rows (16 x 512, hi/lo) into smem once. Row n = gate*4+uu.
    {
        const __nv_bfloat16* whH = g_wh + (size_t)layer * G * WROW;
        const __nv_bfloat16* whL = g_wl + (size_t)layer * G * WROW;
#pragma unroll
        for (int p = 0; p < 4; p++) {
            const int f = tid + p * NTHR;          // 1024 segs per tile
            const int row = f >> 6, seg = f & 63;
            const int g = row >> 2, uu = row & 3;
            const size_t src = (size_t)(g * 512 + u0 + uu) * WROW + 512 + seg * 8;
            const uint32_t dst = (uint32_t)(row * HPITCH + seg * 8) * 2;
            *(uint4*)(dynsm + WS_H + dst) = *(const uint4*)(whH + src);
            *(uint4*)(dynsm + WS_L + dst) = *(const uint4*)(whL + src);
        }
    }

    // Cell state: thread (b, ul) with b = tid>>2, ul = tid&3.
    const int bT = tid >> 2, ulT = tid & 3;
    float cv = c0l[bT * H + u0 + ulT];
    __syncthreads();

    // ldmatrix lane bases (A mapping proven in gemm_hmma; B uses x4 variant)
    const int sel = lane >> 3, lr = lane & 7;
    const uint32_t aRow = (uint32_t)(wm * 16 + (sel & 1) * 8 + lr);
    const uint32_t aCol = (uint32_t)((sel >> 1) * 8);
    const uint32_t aOffH = sb + HS_H + (aRow * HPITCH + wk * 256 + aCol) * 2;
    const uint32_t aOffL = sb + HS_L + (aRow * HPITCH + wk * 256 + aCol) * 2;
    // B x4: m0=(n lr,k0) m1=(n lr,k8) m2=(n lr+8,k0) m3=(n lr+8,k8)
    const uint32_t bRow = (uint32_t)(lr + (sel >> 1) * 8);
    const uint32_t bCol = (uint32_t)((sel & 1) * 8);
    const uint32_t bOffH = sb + WS_H + (bRow * HPITCH + wk * 256 + bCol) * 2;
    const uint32_t bOffL = sb + WS_L + (bRow * HPITCH + wk * 256 + bCol) * 2;

    float* xs   = (float*)(dynsm + XS_OFF);
    float* gred = (float*)(dynsm + GR_OFF);

    // Per-warp h-stage lane mapping (chunked by k within this warp's half):
    // chunk c covers cols [wk*256 + c*128, +128). Lane handles rows p*2+(lane>>4),
    // col seg (lane&15)*8, p = 0..7.
    const int stRow0 = wm * 16 + (lane >> 4);      // + p*2
    const int stCol  = (lane & 15) * 8;            // + wk*256 + c*128

    for (int t = 0; t < S; t++) {
        const int rbuf = (t + 1) & 1, wbuf = t & 1;

        // Groups 1,2: h stage chunks (hi+lo). Group 3: xg.
        {
            const __nv_bfloat16* srcH = g_hbf[rbuf][0];
            const __nv_bfloat16* srcL = g_hbf[rbuf][1];
#pragma unroll
            for (int c = 0; c < 2; c++) {
#pragma unroll
                for (int p = 0; p < 8; p++) {
                    const int row = stRow0 + p * 2;
                    const int col = wk * 256 + c * 128 + stCol;
                    const uint32_t dst = sb + HS_H +
                        ((uint32_t)(row * HPITCH + col)) * 2;
                    const size_t src = (size_t)row * 512 + col;
                    CPASYNC(dst, srcH + src);
                    CPASYNC(dst + (HS_L - HS_H), srcL + src);
                }
                CPCOMMIT();
            }
        }
        CPASYNC(sb + XS_OFF + (uint32_t)(bT * 16 + ulT * 4) * 4,
                g_xg + (size_t)t * B * G + bT * G + ulT * 512 + u0);
        CPCOMMIT();

        CPWAIT(2);        // chunk0 arrived (chunk1 + xg still pending)
        __syncwarp();

        float dm[2][4] = {}, dc[2][4] = {};
#pragma unroll
        for (int ks = 0; ks < 8; ks++) {
            uint32_t ah[4], al[4], bh[4], bl[4];
            LDSM4(ah[0], ah[1], ah[2], ah[3], aOffH + ks * 32);
            LDSM4(al[0], al[1], al[2], al[3], aOffL + ks * 32);
            LDSM4(bh[0], bh[1], bh[2], bh[3], bOffH + ks * 32);
            LDSM4(bl[0], bl[1], bl[2], bl[3], bOffL + ks * 32);
            MMA16816(dm[0], ah, bh);
            MMA16816(dm[1], ah, bh + 2);
            MMA16816(dc[0], ah, bl);
            MMA16816(dc[1], ah, bl + 2);
            MMA16816(dc[0], al, bh);
            MMA16816(dc[1], al, bh + 2);
        }

        CPWAIT(1);        // chunk1 arrived (xg still pending)
        __syncwarp();
#pragma unroll
        for (int ks = 8; ks < 16; ks++) {
            uint32_t ah[4], al[4], bh[4], bl[4];
            LDSM4(ah[0], ah[1], ah[2], ah[3], aOffH + ks * 32);
            LDSM4(al[0], al[1], al[2], al[3], aOffL + ks * 32);
            LDSM4(bh[0], bh[1], bh[2], bh[3], bOffH + ks * 32);
            LDSM4(bl[0], bl[1], bl[2], bl[3], bOffL + ks * 32);
            MMA16816(dm[0], ah, bh);
            MMA16816(dm[1], ah, bh + 2);
            MMA16816(dc[0], ah, bl);
            MMA16816(dc[1], ah, bl + 2);
            MMA16816(dc[0], al, bh);
            MMA16816(dc[1], al, bh + 2);
        }

        // Both k-halves store partials; elementwise adds them.
        {
            const int gq = lane >> 2, tq = lane & 3;
            float* gr = gred + wk * (64 * 18);
#pragma unroll
            for (int j = 0; j < 2; j++) {
                *(float2*)(&gr[(wm * 16 + gq) * 18 + j * 8 + tq * 2]) =
                    make_float2(dm[j][0] + dc[j][0], dm[j][1] + dc[j][1]);
                *(float2*)(&gr[(wm * 16 + gq + 8) * 18 + j * 8 + tq * 2]) =
                    make_float2(dm[j][2] + dc[j][2], dm[j][3] + dc[j][3]);
            }
        }
        __syncthreads();

        // Elementwise update: thread (bT, ulT)
        {
            CPWAIT(0);        // xg group done (long since, behind mma)
            __syncwarp();
            const int u = u0 + ulT;
            const float gi = gred[bT * 18 +  0 + ulT] + gred[64 * 18 + bT * 18 +  0 + ulT]
                           + xs[bT * 16 +  0 + ulT];
            const float gf = gred[bT * 18 +  4 + ulT] + gred[64 * 18 + bT * 18 +  4 + ulT]
                           + xs[bT * 16 +  4 + ulT];
            const float go = gred[bT * 18 +  8 + ulT] + gred[64 * 18 + bT * 18 +  8 + ulT]
                           + xs[bT * 16 +  8 + ulT];
            const float gg = gred[bT * 18 + 12 + ulT] + gred[64 * 18 + bT * 18 + 12 + ulT]
                           + xs[bT * 16 + 12 + ulT];
            const float i_ = __fdividef(1.f, 1.f + __expf(-gi));
            const float f_ = __fdividef(1.f, 1.f + __expf(-gf));
            const float o_ = __fdividef(1.f, 1.f + __expf(-go));
            const float gv = tanhf(gg);
            cv = f_ * cv + i_ * gv;
            const float hnew = o_ * tanhf(cv);

            __nv_bfloat16 hh, hl;
            bsplit(hnew, hh, hl);
            g_hbf[wbuf][0][bT * H + u] = hh;
            g_hbf[wbuf][1][bT * H + u] = hl;

            if (layer == 0) {
                const size_t o = ((size_t)t * B + bT) * 512 + u;
                g_y1h[o] = hh;
                g_y1l[o] = hl;
            } else {
                dout[(size_t)bT * S * H + (size_t)t * H + u] = hnew;
            }
            if (t == S - 1) {
                const size_t BSH = (size_t)B * S * H, BH = (size_t)B * H;
                dout[BSH + (size_t)layer * BH + bT * H + u] = hnew;
                dout[BSH + 2 * BH + (size_t)layer * BH + bT * H + u] = cv;
            }
        }

        // Grid-wide barrier: distributed per-CTA flags, no atomic contention.
        if (t != S - 1) {
            __syncthreads();
            if (warp == 0) {
                const unsigned tgt = (unsigned)(t + 1);
                if (lane == 0)
                    asm volatile("st.release.gpu.u32 [%0], %1;"
                                 :: "l"(flags + (size_t)blockIdx.x * 32), "r"(tgt)
                                 : "memory");
                const unsigned* f0 = flags + lane * 32;
                bool ok;
                do {
                    unsigned v0, v1, v2, v3;
                    asm volatile("ld.relaxed.gpu.u32 %0, [%1];" : "=r"(v0) : "l"(f0) : "memory");
                    asm volatile("ld.relaxed.gpu.u32 %0, [%1];" : "=r"(v1) : "l"(f0 + 32 * 32) : "memory");
                    asm volatile("ld.relaxed.gpu.u32 %0, [%1];" : "=r"(v2) : "l"(f0 + 64 * 32) : "memory");
                    asm volatile("ld.relaxed.gpu.u32 %0, [%1];" : "=r"(v3) : "l"(f0 + 96 * 32) : "memory");
                    ok = (v0 >= tgt) && (v1 >= tgt) && (v2 >= tgt) && (v3 >= tgt);
                } while (!__all_sync(0xffffffffu, ok));
                asm volatile("fence.acq_rel.gpu;" ::: "memory");
            }
            __syncthreads();
        }
    }
}

// ---------------------------------------------------------------------------
// Launch: split_x, split_w; per layer: GEMM, init_h, persistent recurrence.
// 8 graph nodes. No allocs, no syncs, graph-capturable.
// ---------------------------------------------------------------------------
extern "C" void kernel_launch(void* const* d_in, const int* in_sizes, int n_in,
                              void* d_out, int out_size)
{
    const float* x  = (const float*)d_in[0];
    const float* W  = (const float*)d_in[1];
    const float* bb = (const float*)d_in[2];
    const float* h0 = (const float*)d_in[3];
    const float* c0 = (const float*)d_in[4];
    float* out = (float*)d_out;

    cudaFuncSetAttribute(gemm_hmma, cudaFuncAttributeMaxDynamicSharedMemorySize, GSMEM);
    cudaFuncSetAttribute(lstm_persist, cudaFuncAttributeMaxDynamicSharedMemorySize, P2_SMEM);

    split_x<<<(M_TOT * 512 / 4) / 256, 256>>>(x);
    split_w<<<(2 * G * WROW / 4) / 256, 256>>>(W);

    for (int layer = 0; layer < 2; layer++) {
        gemm_hmma<<<dim3(16, 512), 256, GSMEM>>>(bb + layer * G, layer);
        init_h<<<(B * H) / 256, 256>>>(h0 + (size_t)layer * B * H);
        lstm_persist<<<NCTA, NTHR, P2_SMEM>>>(layer, c0 + (size_t)layer * B * H, out);
    }
}

// round 13
// speedup vs baseline: 1.0222x; 1.0222x over previous
#include <cuda_runtime.h>
#include <cuda_bf16.h>
#include <math.h>
#include <cstdint>

// Problem constants
#define B    64
#define S    1024
#define D    512
#define H    512
#define G    2048      // 4*H
#define WROW 1024      // D+H, row stride of W
#define M_TOT (S*B)    // 65536 GEMM rows, m = t*B + b
#define NCTA 128
#define NTHR 256

// ---------------------------------------------------------------------------
// Scratch (__device__ globals: sanctioned alloc-free workaround)
// ---------------------------------------------------------------------------
__device__ __nv_bfloat16 g_xh [(size_t)M_TOT * 512];     // layer-0 A hi
__device__ __nv_bfloat16 g_xl [(size_t)M_TOT * 512];     // layer-0 A lo
__device__ __nv_bfloat16 g_y1h[(size_t)M_TOT * 512];     // layer-1 A hi
__device__ __nv_bfloat16 g_y1l[(size_t)M_TOT * 512];     // layer-1 A lo
__device__ __nv_bfloat16 g_wh [2 * (size_t)G * WROW];    // W hi, [layer][n][WROW]
__device__ __nv_bfloat16 g_wl [2 * (size_t)G * WROW];    // W lo
__device__ float g_xg[(size_t)S * B * G];                // input gates (t*B+b, G)
__device__ __nv_bfloat16 g_hbf[2][2][B * H];             // ping-pong h, [buf][hi/lo]
__device__ unsigned g_cnt[2][8 * 32];                    // 8 barrier counters, 128B apart

// ---------------------------------------------------------------------------
// PTX helpers (arch-portable: sm_80+ only)
// ---------------------------------------------------------------------------
__device__ __forceinline__ uint32_t smem_u32(const void* p) {
    uint32_t a;
    asm("{ .reg .u64 t; cvta.to.shared.u64 t, %1; cvt.u32.u64 %0, t; }"
        : "=r"(a) : "l"(p));
    return a;
}

#define CPASYNC(sm, gm) \
    asm volatile("cp.async.cg.shared.global [%0], [%1], 16;" :: "r"(sm), "l"(gm))
#define CPCOMMIT() asm volatile("cp.async.commit_group;" ::: "memory")
#define CPWAIT(n)  asm volatile("cp.async.wait_group %0;" :: "n"(n) : "memory")

#define LDSM4(r0, r1, r2, r3, addr) \
    asm volatile("ldmatrix.sync.aligned.m8n8.x4.shared.b16 {%0,%1,%2,%3}, [%4];" \
        : "=r"(r0), "=r"(r1), "=r"(r2), "=r"(r3) : "r"(addr))
#define LDSM2(r0, r1, addr) \
    asm volatile("ldmatrix.sync.aligned.m8n8.x2.shared.b16 {%0,%1}, [%2];" \
        : "=r"(r0), "=r"(r1) : "r"(addr))

#define MMA16816(d, a, b) \
    asm volatile("mma.sync.aligned.m16n8k16.row.col.f32.bf16.bf16.f32 " \
        "{%0,%1,%2,%3},{%4,%5,%6,%7},{%8,%9},{%0,%1,%2,%3};" \
        : "+f"((d)[0]), "+f"((d)[1]), "+f"((d)[2]), "+f"((d)[3]) \
        : "r"((a)[0]), "r"((a)[1]), "r"((a)[2]), "r"((a)[3]), \
          "r"((b)[0]), "r"((b)[1]))

__device__ __forceinline__ void bsplit(float v, __nv_bfloat16& h, __nv_bfloat16& l) {
    h = __float2bfloat16(v);
    l = __float2bfloat16(v - __bfloat162float(h));
}

// ---------------------------------------------------------------------------
// Split kernels: fp32 -> bf16 hi/lo
// ---------------------------------------------------------------------------
__global__ void __launch_bounds__(256) split_x(const float* __restrict__ x)
{
    const size_t i4 = (size_t)blockIdx.x * 256 + threadIdx.x;  // over M_TOT*512/4
    const float4 v = ((const float4*)x)[i4];
    const size_t idx = i4 * 4;                 // (b, t, k) in x layout
    const int k = (int)(idx & 511);
    const int t = (int)((idx >> 9) & 1023);
    const int b = (int)(idx >> 19);
    const size_t o = ((size_t)t * B + b) * 512 + k;   // GEMM A layout (m, k)
    __nv_bfloat16 h0, l0, h1, l1, h2, l2, h3, l3;
    bsplit(v.x, h0, l0); bsplit(v.y, h1, l1);
    bsplit(v.z, h2, l2); bsplit(v.w, h3, l3);
    __nv_bfloat162 a, bb2;
    a.x = h0; a.y = h1; bb2.x = h2; bb2.y = h3;
    *(__nv_bfloat162*)(g_xh + o)     = a;
    *(__nv_bfloat162*)(g_xh + o + 2) = bb2;
    a.x = l0; a.y = l1; bb2.x = l2; bb2.y = l3;
    *(__nv_bfloat162*)(g_xl + o)     = a;
    *(__nv_bfloat162*)(g_xl + o + 2) = bb2;
}

// Full-W split: source layout [layer][n][WROW] is copied linearly.
__global__ void __launch_bounds__(256) split_w(const float* __restrict__ W)
{
    const size_t i4 = (size_t)blockIdx.x * 256 + threadIdx.x;  // over 2*G*WROW/4
    const float4 v = ((const float4*)W)[i4];
    const size_t idx = i4 * 4;
    __nv_bfloat16 h0, l0, h1, l1, h2, l2, h3, l3;
    bsplit(v.x, h0, l0); bsplit(v.y, h1, l1);
    bsplit(v.z, h2, l2); bsplit(v.w, h3, l3);
    __nv_bfloat162 a, bb2;
    a.x = h0; a.y = h1; bb2.x = h2; bb2.y = h3;
    *(__nv_bfloat162*)(g_wh + idx)     = a;
    *(__nv_bfloat162*)(g_wh + idx + 2) = bb2;
    a.x = l0; a.y = l1; bb2.x = l2; bb2.y = l3;
    *(__nv_bfloat162*)(g_wl + idx)     = a;
    *(__nv_bfloat162*)(g_wl + idx + 2) = bb2;
}

// Convert h0 (fp32) into the bf16 ping-pong buffer read at t=0 (index 1).
__global__ void __launch_bounds__(256) init_h(const float* __restrict__ h0l)
{
    const int i = blockIdx.x * 256 + threadIdx.x;   // 0..B*H-1
    __nv_bfloat16 hh, hl;
    bsplit(h0l[i], hh, hl);
    g_hbf[1][0][i] = hh;
    g_hbf[1][1][i] = hl;
}

// ---------------------------------------------------------------------------
// HMMA bf16-split GEMM: xg[m][n] = sum_k A[m][k]*Wx[n][k] + bias[n]
// (unchanged — proven; also zeroes this layer's barrier counters)
// ---------------------------------------------------------------------------
#define APITCH 72
#define ATILEB (128 * APITCH * 2)        // 18432 B per operand tile
#define STAGEB (2 * ATILEB)              // A + B per stage
#define GSMEM  (2 * STAGEB)              // double buffered = 73728 B

__global__ void __launch_bounds__(256) gemm_hmma(
    const float* __restrict__ bias, int layer)
{
    if (blockIdx.x == 0 && blockIdx.y == 0 && threadIdx.x < 8)
        g_cnt[layer][threadIdx.x * 32] = 0u;   // reset barrier counters

    const __nv_bfloat16* __restrict__ Ah = layer ? g_y1h : g_xh;
    const __nv_bfloat16* __restrict__ Al = layer ? g_y1l : g_xl;
    const __nv_bfloat16* __restrict__ Bh = g_wh + (size_t)layer * G * WROW;
    const __nv_bfloat16* __restrict__ Bl = g_wl + (size_t)layer * G * WROW;
    const __nv_bfloat16* APs[3] = { Ah, Ah, Al };
    const __nv_bfloat16* BPs[3] = { Bh, Bl, Bh };

    extern __shared__ char dynsm[];
    const uint32_t sbase = smem_u32(dynsm);
    const int tid = threadIdx.x, lane = tid & 31, warp = tid >> 5;
    const int wm = warp & 1, wn = warp >> 1;          // warp grid 2(M) x 4(N)
    const int m0 = blockIdx.y * 128, n0 = blockIdx.x * 128;

    const int sel = lane >> 3, lr = lane & 7;
    const uint32_t aRow  = wm * 64 + (sel & 1) * 8 + lr;
    const uint32_t aColB = (sel >> 1) * 8;
    const uint32_t bRow  = wn * 32 + lr;
    const uint32_t bColB = (sel & 1) * 8;

    float d[4][4][4];
#pragma unroll
    for (int i = 0; i < 4; i++)
#pragma unroll
        for (int j = 0; j < 4; j++)
#pragma unroll
            for (int q = 0; q < 4; q++) d[i][j][q] = 0.0f;

    auto issue = [&](int c, int buf) {
        const int term = c >> 3, kg = (c & 7) * 64;
        const __nv_bfloat16* Ap = APs[term];
        const __nv_bfloat16* Bp = BPs[term];
        const uint32_t sA = sbase + buf * STAGEB;
        const uint32_t sB = sA + ATILEB;
#pragma unroll
        for (int p = 0; p < 4; p++) {
            const int f = tid + p * 256;
            const int row = f >> 3, seg = f & 7;
            const uint32_t so = (uint32_t)(row * APITCH + seg * 8) * 2;
            CPASYNC(sA + so, Ap + (size_t)(m0 + row) * 512 + kg + seg * 8);
            CPASYNC(sB + so, Bp + (size_t)(n0 + row) * WROW + kg + seg * 8);
        }
        CPCOMMIT();
    };

    issue(0, 0);
    for (int c = 0; c < 24; c++) {
        const int buf = c & 1;
        if (c + 1 < 24) { issue(c + 1, buf ^ 1); CPWAIT(1); }
        else            { CPWAIT(0); }
        __syncthreads();

        const uint32_t sA = sbase + buf * STAGEB;
        const uint32_t sB = sA + ATILEB;
        const uint32_t aBase = sA + (aRow * APITCH + aColB) * 2;
        const uint32_t bBase = sB + (bRow * APITCH + bColB) * 2;

#pragma unroll
        for (int ks = 0; ks < 4; ks++) {
            uint32_t a[4][4], b[4][2];
#pragma unroll
            for (int i = 0; i < 4; i++)
                LDSM4(a[i][0], a[i][1], a[i][2], a[i][3],
                      aBase + (uint32_t)(i * 16 * APITCH + ks * 16) * 2);
#pragma unroll
            for (int j = 0; j < 4; j++)
                LDSM2(b[j][0], b[j][1],
                      bBase + (uint32_t)(j * 8 * APITCH + ks * 16) * 2);
#pragma unroll
            for (int i = 0; i < 4; i++)
#pragma unroll
                for (int j = 0; j < 4; j++)
                    MMA16816(d[i][j], a[i], b[j]);
        }
        __syncthreads();
    }

    const int gq = lane >> 2, tq = lane & 3;
#pragma unroll
    for (int i = 0; i < 4; i++) {
#pragma unroll
        for (int j = 0; j < 4; j++) {
            const int col = n0 + wn * 32 + j * 8 + tq * 2;
            const int row0 = m0 + wm * 64 + i * 16 + gq;
            const float b0 = bias[col], b1 = bias[col + 1];
            float2 v0, v1;
            v0.x = d[i][j][0] + b0; v0.y = d[i][j][1] + b1;
            v1.x = d[i][j][2] + b0; v1.y = d[i][j][3] + b1;
            *(float2*)(g_xg + (size_t)row0 * G + col) = v0;
            *(float2*)(g_xg + (size_t)(row0 + 8) * G + col) = v1;
        }
    }
}

// ---------------------------------------------------------------------------
// Persistent HMMA recurrence (R9 base, proven 14.19ms):
//  - per-warp one-shot self-staging of its own h region (no stage sync)
//  - xg via cp.async group waited only before elementwise
//  - B via LDSM4; single-pass gred; 1 block sync + barrier syncs
//  R12 delta: hybrid 8-counter grid barrier (spread atomic contention 16x,
//  cheap 8-line poll) replacing the single-counter barrier.
// ---------------------------------------------------------------------------
#define HPITCH 520                       // halves per row: 1040 B
#define HS_H   0
#define HS_L   (HS_H + 64 * HPITCH * 2)      // 66560
#define WS_H   (HS_L + 64 * HPITCH * 2)      // 133120
#define WS_L   (WS_H + 16 * HPITCH * 2)      // 149760
#define XS_OFF (WS_L + 16 * HPITCH * 2)      // 166400, [64][16] fp32
#define GR_OFF (XS_OFF + 64 * 16 * 4)        // 170496, [2][64][18] fp32
#define P2_SMEM (GR_OFF + 2 * 64 * 18 * 4)   // 179712 B

__global__ void __launch_bounds__(NTHR, 1) lstm_persist(
    int layer,
    const float* __restrict__ c0l,
    float* __restrict__ dout)
{
    extern __shared__ char dynsm[];
    const uint32_t sb = smem_u32(dynsm);
    const int tid = threadIdx.x, lane = tid & 31, warp = tid >> 5;
    const int wm = warp & 3;            // m-tile: batches [wm*16, wm*16+16)
    const int wk = warp >> 2;           // k-half: k in [wk*256, wk*256+256)
    const int u0 = blockIdx.x * 4;
    unsigned* cnts = g_cnt[layer];
    unsigned* mycnt = cnts + (blockIdx.x & 7) * 32;

    // --- Stage Wh rows (16 x 512, hi/lo) into smem once. Row n = gate*4+uu.
    {
        const __nv_bfloat16* whH = g_wh + (size_t)layer * G * WROW;
        const __nv_bfloat16* whL = g_wl + (size_t)layer * G * WROW;
#pragma unroll
        for (int p = 0; p < 4; p++) {
            const int f = tid + p * NTHR;          // 1024 segs per tile
            const int row = f >> 6, seg = f & 63;
            const int g = row >> 2, uu = row & 3;
            const size_t src = (size_t)(g * 512 + u0 + uu) * WROW + 512 + seg * 8;
            const uint32_t dst = (uint32_t)(row * HPITCH + seg * 8) * 2;
            *(uint4*)(dynsm + WS_H + dst) = *(const uint4*)(whH + src);
            *(uint4*)(dynsm + WS_L + dst) = *(const uint4*)(whL + src);
        }
    }

    // Cell state: thread (b, ul) with b = tid>>2, ul = tid&3.
    const int bT = tid >> 2, ulT = tid & 3;
    float cv = c0l[bT * H + u0 + ulT];
    __syncthreads();

    // ldmatrix lane bases (A mapping proven in gemm_hmma; B uses x4 variant)
    const int sel = lane >> 3, lr = lane & 7;
    const uint32_t aRow = (uint32_t)(wm * 16 + (sel & 1) * 8 + lr);
    const uint32_t aCol = (uint32_t)((sel >> 1) * 8);
    const uint32_t aOffH = sb + HS_H + (aRow * HPITCH + wk * 256 + aCol) * 2;
    const uint32_t aOffL = sb + HS_L + (aRow * HPITCH + wk * 256 + aCol) * 2;
    // B x4: m0=(n lr,k0) m1=(n lr,k8) m2=(n lr+8,k0) m3=(n lr+8,k8)
    const uint32_t bRow = (uint32_t)(lr + (sel >> 1) * 8);
    const uint32_t bCol = (uint32_t)((sel & 1) * 8);
    const uint32_t bOffH = sb + WS_H + (bRow * HPITCH + wk * 256 + bCol) * 2;
    const uint32_t bOffL = sb + WS_L + (bRow * HPITCH + wk * 256 + bCol) * 2;

    float* xs   = (float*)(dynsm + XS_OFF);
    float* gred = (float*)(dynsm + GR_OFF);

    // Per-warp h-stage bases (each warp stages its own disjoint region)
    const uint32_t stHd = sb + HS_H + ((uint32_t)(wm * 16) * HPITCH + wk * 256) * 2 + lane * 16;
    const uint32_t stLd = sb + HS_L + ((uint32_t)(wm * 16) * HPITCH + wk * 256) * 2 + lane * 16;
    const size_t   stSrc = (size_t)(wm * 16) * 512 + wk * 256 + lane * 8;

    for (int t = 0; t < S; t++) {
        const int rbuf = (t + 1) & 1, wbuf = t & 1;

        // Group 1: h stage (own warp's 16 rows x 256 halves, hi+lo)
        {
            const __nv_bfloat16* srcH = g_hbf[rbuf][0] + stSrc;
            const __nv_bfloat16* srcL = g_hbf[rbuf][1] + stSrc;
#pragma unroll
            for (int i = 0; i < 16; i++) {
                CPASYNC(stHd + (uint32_t)(i * HPITCH) * 2, srcH + (size_t)i * 512);
                CPASYNC(stLd + (uint32_t)(i * HPITCH) * 2, srcL + (size_t)i * 512);
            }
            CPCOMMIT();
        }
        // Group 2 (newest): xg -> xs (DRAM; waited only before elementwise)
        CPASYNC(sb + XS_OFF + (uint32_t)(bT * 16 + ulT * 4) * 4,
                g_xg + (size_t)t * B * G + bT * G + ulT * 512 + u0);
        CPCOMMIT();

        CPWAIT(1);        // wait h group only (xg still pending)
        __syncwarp();

        // 16 k-steps x (AhBh -> main, AhBl + AlBh -> corr)
        float dm[2][4] = {}, dc[2][4] = {};
#pragma unroll
        for (int ks = 0; ks < 16; ks++) {
            uint32_t ah[4], al[4], bh[4], bl[4];
            LDSM4(ah[0], ah[1], ah[2], ah[3], aOffH + ks * 32);
            LDSM4(al[0], al[1], al[2], al[3], aOffL + ks * 32);
            LDSM4(bh[0], bh[1], bh[2], bh[3], bOffH + ks * 32);
            LDSM4(bl[0], bl[1], bl[2], bl[3], bOffL + ks * 32);
            MMA16816(dm[0], ah, bh);
            MMA16816(dm[1], ah, bh + 2);
            MMA16816(dc[0], ah, bl);
            MMA16816(dc[1], ah, bl + 2);
            MMA16816(dc[0], al, bh);
            MMA16816(dc[1], al, bh + 2);
        }

        // Both k-halves store partials; elementwise adds them.
        {
            const int gq = lane >> 2, tq = lane & 3;
            float* gr = gred + wk * (64 * 18);
#pragma unroll
            for (int j = 0; j < 2; j++) {
                *(float2*)(&gr[(wm * 16 + gq) * 18 + j * 8 + tq * 2]) =
                    make_float2(dm[j][0] + dc[j][0], dm[j][1] + dc[j][1]);
                *(float2*)(&gr[(wm * 16 + gq + 8) * 18 + j * 8 + tq * 2]) =
                    make_float2(dm[j][2] + dc[j][2], dm[j][3] + dc[j][3]);
            }
        }
        __syncthreads();

        // Elementwise update: thread (bT, ulT)
        {
            CPWAIT(0);        // xg group done (long since, behind mma)
            __syncwarp();
            const int u = u0 + ulT;
            const float gi = gred[bT * 18 +  0 + ulT] + gred[64 * 18 + bT * 18 +  0 + ulT]
                           + xs[bT * 16 +  0 + ulT];
            const float gf = gred[bT * 18 +  4 + ulT] + gred[64 * 18 + bT * 18 +  4 + ulT]
                           + xs[bT * 16 +  4 + ulT];
            const float go = gred[bT * 18 +  8 + ulT] + gred[64 * 18 + bT * 18 +  8 + ulT]
                           + xs[bT * 16 +  8 + ulT];
            const float gg = gred[bT * 18 + 12 + ulT] + gred[64 * 18 + bT * 18 + 12 + ulT]
                           + xs[bT * 16 + 12 + ulT];
            const float i_ = __fdividef(1.f, 1.f + __expf(-gi));
            const float f_ = __fdividef(1.f, 1.f + __expf(-gf));
            const float o_ = __fdividef(1.f, 1.f + __expf(-go));
            const float gv = tanhf(gg);
            cv = f_ * cv + i_ * gv;
            const float hnew = o_ * tanhf(cv);

            __nv_bfloat16 hh, hl;
            bsplit(hnew, hh, hl);
            g_hbf[wbuf][0][bT * H + u] = hh;
            g_hbf[wbuf][1][bT * H + u] = hl;

            if (layer == 0) {
                const size_t o = ((size_t)t * B + bT) * 512 + u;
                g_y1h[o] = hh;
                g_y1l[o] = hl;
            } else {
                dout[(size_t)bT * S * H + (size_t)t * H + u] = hnew;
            }
            if (t == S - 1) {
                const size_t BSH = (size_t)B * S * H, BH = (size_t)B * H;
                dout[BSH + (size_t)layer * BH + bT * H + u] = hnew;
                dout[BSH + 2 * BH + (size_t)layer * BH + bT * H + u] = cv;
            }
        }

        // Grid-wide barrier: 8 spread counters (16 CTAs each), sum-poll.
        if (t != S - 1) {
            __syncthreads();
            if (tid == 0) {
                asm volatile("red.release.gpu.add.u32 [%0], %1;"
                             :: "l"(mycnt), "r"(1u) : "memory");
                const unsigned tgt = (unsigned)(t + 1) * NCTA;
                unsigned s;
                do {
                    unsigned v0, v1, v2, v3, v4, v5, v6, v7;
                    asm volatile("ld.relaxed.gpu.u32 %0, [%1];" : "=r"(v0) : "l"(cnts +   0) : "memory");
                    asm volatile("ld.relaxed.gpu.u32 %0, [%1];" : "=r"(v1) : "l"(cnts +  32) : "memory");
                    asm volatile("ld.relaxed.gpu.u32 %0, [%1];" : "=r"(v2) : "l"(cnts +  64) : "memory");
                    asm volatile("ld.relaxed.gpu.u32 %0, [%1];" : "=r"(v3) : "l"(cnts +  96) : "memory");
                    asm volatile("ld.relaxed.gpu.u32 %0, [%1];" : "=r"(v4) : "l"(cnts + 128) : "memory");
                    asm volatile("ld.relaxed.gpu.u32 %0, [%1];" : "=r"(v5) : "l"(cnts + 160) : "memory");
                    asm volatile("ld.relaxed.gpu.u32 %0, [%1];" : "=r"(v6) : "l"(cnts + 192) : "memory");
                    asm volatile("ld.relaxed.gpu.u32 %0, [%1];" : "=r"(v7) : "l"(cnts + 224) : "memory");
                    s = ((v0 + v1) + (v2 + v3)) + ((v4 + v5) + (v6 + v7));
                } while (s < tgt);
                asm volatile("fence.acq_rel.gpu;" ::: "memory");
            }
            __syncthreads();
        }
    }
}

// ---------------------------------------------------------------------------
// Launch: split_x, split_w; per layer: GEMM, init_h, persistent recurrence.
// 8 graph nodes. No allocs, no syncs, graph-capturable.
// ---------------------------------------------------------------------------
extern "C" void kernel_launch(void* const* d_in, const int* in_sizes, int n_in,
                              void* d_out, int out_size)
{
    const float* x  = (const float*)d_in[0];
    const float* W  = (const float*)d_in[1];
    const float* bb = (const float*)d_in[2];
    const float* h0 = (const float*)d_in[3];
    const float* c0 = (const float*)d_in[4];
    float* out = (float*)d_out;

    cudaFuncSetAttribute(gemm_hmma, cudaFuncAttributeMaxDynamicSharedMemorySize, GSMEM);
    cudaFuncSetAttribute(lstm_persist, cudaFuncAttributeMaxDynamicSharedMemorySize, P2_SMEM);

    split_x<<<(M_TOT * 512 / 4) / 256, 256>>>(x);
    split_w<<<(2 * G * WROW / 4) / 256, 256>>>(W);

    for (int layer = 0; layer < 2; layer++) {
        gemm_hmma<<<dim3(16, 512), 256, GSMEM>>>(bb + layer * G, layer);
        init_h<<<(B * H) / 256, 256>>>(h0 + (size_t)layer * B * H);
        lstm_persist<<<NCTA, NTHR, P2_SMEM>>>(layer, c0 + (size_t)layer * B * H, out);
    }
}

// round 14
// speedup vs baseline: 1.1199x; 1.0956x over previous
#include <cuda_runtime.h>
#include <cuda_bf16.h>
#include <math.h>
#include <cstdint>

// Problem constants
#define B    64
#define S    1024
#define D    512
#define H    512
#define G    2048      // 4*H
#define WROW 1024      // D+H, row stride of W
#define M_TOT (S*B)    // 65536 GEMM rows, m = t*B + b
#define NCTA 128
#define NTHR 256

// ---------------------------------------------------------------------------
// Scratch (__device__ globals: sanctioned alloc-free workaround)
// ---------------------------------------------------------------------------
__device__ __nv_bfloat16 g_xh [(size_t)M_TOT * 512];     // layer-0 A hi
__device__ __nv_bfloat16 g_xl [(size_t)M_TOT * 512];     // layer-0 A lo
__device__ __nv_bfloat16 g_y1h[(size_t)M_TOT * 512];     // layer-1 A hi
__device__ __nv_bfloat16 g_y1l[(size_t)M_TOT * 512];     // layer-1 A lo
__device__ __nv_bfloat16 g_wh [2 * (size_t)G * WROW];    // W hi, [layer][n][WROW]
__device__ __nv_bfloat16 g_wl [2 * (size_t)G * WROW];    // W lo
__device__ float g_xg[(size_t)S * B * G];                // input gates (t*B+b, G)
__device__ __nv_bfloat16 g_hbf[2][2][B * H];             // ping-pong h, [buf][hi/lo]
__device__ unsigned g_bar[2];                            // grid-barrier counters

// ---------------------------------------------------------------------------
// PTX helpers (arch-portable: sm_80+ only)
// ---------------------------------------------------------------------------
__device__ __forceinline__ uint32_t smem_u32(const void* p) {
    uint32_t a;
    asm("{ .reg .u64 t; cvta.to.shared.u64 t, %1; cvt.u32.u64 %0, t; }"
        : "=r"(a) : "l"(p));
    return a;
}

#define CPASYNC(sm, gm) \
    asm volatile("cp.async.cg.shared.global [%0], [%1], 16;" :: "r"(sm), "l"(gm))
#define CPCOMMIT() asm volatile("cp.async.commit_group;" ::: "memory")
#define CPWAIT(n)  asm volatile("cp.async.wait_group %0;" :: "n"(n) : "memory")

#define LDSM4(r0, r1, r2, r3, addr) \
    asm volatile("ldmatrix.sync.aligned.m8n8.x4.shared.b16 {%0,%1,%2,%3}, [%4];" \
        : "=r"(r0), "=r"(r1), "=r"(r2), "=r"(r3) : "r"(addr))
#define LDSM2(r0, r1, addr) \
    asm volatile("ldmatrix.sync.aligned.m8n8.x2.shared.b16 {%0,%1}, [%2];" \
        : "=r"(r0), "=r"(r1) : "r"(addr))

#define MMA16816(d, a, b) \
    asm volatile("mma.sync.aligned.m16n8k16.row.col.f32.bf16.bf16.f32 " \
        "{%0,%1,%2,%3},{%4,%5,%6,%7},{%8,%9},{%0,%1,%2,%3};" \
        : "+f"((d)[0]), "+f"((d)[1]), "+f"((d)[2]), "+f"((d)[3]) \
        : "r"((a)[0]), "r"((a)[1]), "r"((a)[2]), "r"((a)[3]), \
          "r"((b)[0]), "r"((b)[1]))

__device__ __forceinline__ void bsplit(float v, __nv_bfloat16& h, __nv_bfloat16& l) {
    h = __float2bfloat16(v);
    l = __float2bfloat16(v - __bfloat162float(h));
}

// ---------------------------------------------------------------------------
// Split kernels: fp32 -> bf16 hi/lo
// ---------------------------------------------------------------------------
__global__ void __launch_bounds__(256) split_x(const float* __restrict__ x)
{
    const size_t i4 = (size_t)blockIdx.x * 256 + threadIdx.x;  // over M_TOT*512/4
    const float4 v = ((const float4*)x)[i4];
    const size_t idx = i4 * 4;                 // (b, t, k) in x layout
    const int k = (int)(idx & 511);
    const int t = (int)((idx >> 9) & 1023);
    const int b = (int)(idx >> 19);
    const size_t o = ((size_t)t * B + b) * 512 + k;   // GEMM A layout (m, k)
    __nv_bfloat16 h0, l0, h1, l1, h2, l2, h3, l3;
    bsplit(v.x, h0, l0); bsplit(v.y, h1, l1);
    bsplit(v.z, h2, l2); bsplit(v.w, h3, l3);
    __nv_bfloat162 a, bb2;
    a.x = h0; a.y = h1; bb2.x = h2; bb2.y = h3;
    *(__nv_bfloat162*)(g_xh + o)     = a;
    *(__nv_bfloat162*)(g_xh + o + 2) = bb2;
    a.x = l0; a.y = l1; bb2.x = l2; bb2.y = l3;
    *(__nv_bfloat162*)(g_xl + o)     = a;
    *(__nv_bfloat162*)(g_xl + o + 2) = bb2;
}

// Full-W split: source layout [layer][n][WROW] is copied linearly.
__global__ void __launch_bounds__(256) split_w(const float* __restrict__ W)
{
    const size_t i4 = (size_t)blockIdx.x * 256 + threadIdx.x;  // over 2*G*WROW/4
    const float4 v = ((const float4*)W)[i4];
    const size_t idx = i4 * 4;
    __nv_bfloat16 h0, l0, h1, l1, h2, l2, h3, l3;
    bsplit(v.x, h0, l0); bsplit(v.y, h1, l1);
    bsplit(v.z, h2, l2); bsplit(v.w, h3, l3);
    __nv_bfloat162 a, bb2;
    a.x = h0; a.y = h1; bb2.x = h2; bb2.y = h3;
    *(__nv_bfloat162*)(g_wh + idx)     = a;
    *(__nv_bfloat162*)(g_wh + idx + 2) = bb2;
    a.x = l0; a.y = l1; bb2.x = l2; bb2.y = l3;
    *(__nv_bfloat162*)(g_wl + idx)     = a;
    *(__nv_bfloat162*)(g_wl + idx + 2) = bb2;
}

// Convert h0 (fp32) into the bf16 ping-pong buffer read at t=0 (index 1).
__global__ void __launch_bounds__(256) init_h(const float* __restrict__ h0l)
{
    const int i = blockIdx.x * 256 + threadIdx.x;   // 0..B*H-1
    __nv_bfloat16 hh, hl;
    bsplit(h0l[i], hh, hl);
    g_hbf[1][0][i] = hh;
    g_hbf[1][1][i] = hl;
}

// ---------------------------------------------------------------------------
// HMMA bf16-split GEMM: xg[m][n] = sum_k A[m][k]*Wx[n][k] + bias[n]
// (unchanged — proven; also zeroes this layer's barrier counter)
// ---------------------------------------------------------------------------
#define APITCH 72
#define ATILEB (128 * APITCH * 2)        // 18432 B per operand tile
#define STAGEB (2 * ATILEB)              // A + B per stage
#define GSMEM  (2 * STAGEB)              // double buffered = 73728 B

__global__ void __launch_bounds__(256) gemm_hmma(
    const float* __restrict__ bias, int layer)
{
    if (blockIdx.x == 0 && blockIdx.y == 0 && threadIdx.x == 0)
        g_bar[layer] = 0u;               // reset grid barrier for this layer

    const __nv_bfloat16* __restrict__ Ah = layer ? g_y1h : g_xh;
    const __nv_bfloat16* __restrict__ Al = layer ? g_y1l : g_xl;
    const __nv_bfloat16* __restrict__ Bh = g_wh + (size_t)layer * G * WROW;
    const __nv_bfloat16* __restrict__ Bl = g_wl + (size_t)layer * G * WROW;
    const __nv_bfloat16* APs[3] = { Ah, Ah, Al };
    const __nv_bfloat16* BPs[3] = { Bh, Bl, Bh };

    extern __shared__ char dynsm[];
    const uint32_t sbase = smem_u32(dynsm);
    const int tid = threadIdx.x, lane = tid & 31, warp = tid >> 5;
    const int wm = warp & 1, wn = warp >> 1;          // warp grid 2(M) x 4(N)
    const int m0 = blockIdx.y * 128, n0 = blockIdx.x * 128;

    const int sel = lane >> 3, lr = lane & 7;
    const uint32_t aRow  = wm * 64 + (sel & 1) * 8 + lr;
    const uint32_t aColB = (sel >> 1) * 8;
    const uint32_t bRow  = wn * 32 + lr;
    const uint32_t bColB = (sel & 1) * 8;

    float d[4][4][4];
#pragma unroll
    for (int i = 0; i < 4; i++)
#pragma unroll
        for (int j = 0; j < 4; j++)
#pragma unroll
            for (int q = 0; q < 4; q++) d[i][j][q] = 0.0f;

    auto issue = [&](int c, int buf) {
        const int term = c >> 3, kg = (c & 7) * 64;
        const __nv_bfloat16* Ap = APs[term];
        const __nv_bfloat16* Bp = BPs[term];
        const uint32_t sA = sbase + buf * STAGEB;
        const uint32_t sB = sA + ATILEB;
#pragma unroll
        for (int p = 0; p < 4; p++) {
            const int f = tid + p * 256;
            const int row = f >> 3, seg = f & 7;
            const uint32_t so = (uint32_t)(row * APITCH + seg * 8) * 2;
            CPASYNC(sA + so, Ap + (size_t)(m0 + row) * 512 + kg + seg * 8);
            CPASYNC(sB + so, Bp + (size_t)(n0 + row) * WROW + kg + seg * 8);
        }
        CPCOMMIT();
    };

    issue(0, 0);
    for (int c = 0; c < 24; c++) {
        const int buf = c & 1;
        if (c + 1 < 24) { issue(c + 1, buf ^ 1); CPWAIT(1); }
        else            { CPWAIT(0); }
        __syncthreads();

        const uint32_t sA = sbase + buf * STAGEB;
        const uint32_t sB = sA + ATILEB;
        const uint32_t aBase = sA + (aRow * APITCH + aColB) * 2;
        const uint32_t bBase = sB + (bRow * APITCH + bColB) * 2;

#pragma unroll
        for (int ks = 0; ks < 4; ks++) {
            uint32_t a[4][4], b[4][2];
#pragma unroll
            for (int i = 0; i < 4; i++)
                LDSM4(a[i][0], a[i][1], a[i][2], a[i][3],
                      aBase + (uint32_t)(i * 16 * APITCH + ks * 16) * 2);
#pragma unroll
            for (int j = 0; j < 4; j++)
                LDSM2(b[j][0], b[j][1],
                      bBase + (uint32_t)(j * 8 * APITCH + ks * 16) * 2);
#pragma unroll
            for (int i = 0; i < 4; i++)
#pragma unroll
                for (int j = 0; j < 4; j++)
                    MMA16816(d[i][j], a[i], b[j]);
        }
        __syncthreads();
    }

    const int gq = lane >> 2, tq = lane & 3;
#pragma unroll
    for (int i = 0; i < 4; i++) {
#pragma unroll
        for (int j = 0; j < 4; j++) {
            const int col = n0 + wn * 32 + j * 8 + tq * 2;
            const int row0 = m0 + wm * 64 + i * 16 + gq;
            const float b0 = bias[col], b1 = bias[col + 1];
            float2 v0, v1;
            v0.x = d[i][j][0] + b0; v0.y = d[i][j][1] + b1;
            v1.x = d[i][j][2] + b0; v1.y = d[i][j][3] + b1;
            *(float2*)(g_xg + (size_t)row0 * G + col) = v0;
            *(float2*)(g_xg + (size_t)(row0 + 8) * G + col) = v1;
        }
    }
}

// ---------------------------------------------------------------------------
// Persistent HMMA recurrence (R9 base = best at 14.19ms) + R13 delta:
// Wh fragments held in REGISTERS permanently (loaded once via ldmatrix at
// init). Steady-state loop: 2 LDSM4 (ah, al) + 6 mma per ks — smem ldmatrix
// traffic per step halves. Barrier = R9's proven single-counter release/acq.
// ---------------------------------------------------------------------------
#define HPITCH 520                       // halves per row: 1040 B
#define HS_H   0
#define HS_L   (HS_H + 64 * HPITCH * 2)      // 66560
#define WS_H   (HS_L + 64 * HPITCH * 2)      // 133120 (init-only staging)
#define WS_L   (WS_H + 16 * HPITCH * 2)      // 149760
#define XS_OFF (WS_L + 16 * HPITCH * 2)      // 166400, [64][16] fp32
#define GR_OFF (XS_OFF + 64 * 16 * 4)        // 170496, [2][64][18] fp32
#define P2_SMEM (GR_OFF + 2 * 64 * 18 * 4)   // 179712 B

__global__ void __launch_bounds__(NTHR, 1) lstm_persist(
    int layer,
    const float* __restrict__ c0l,
    float* __restrict__ dout)
{
    extern __shared__ char dynsm[];
    const uint32_t sb = smem_u32(dynsm);
    const int tid = threadIdx.x, lane = tid & 31, warp = tid >> 5;
    const int wm = warp & 3;            // m-tile: batches [wm*16, wm*16+16)
    const int wk = warp >> 2;           // k-half: k in [wk*256, wk*256+256)
    const int u0 = blockIdx.x * 4;
    unsigned* bar = &g_bar[layer];

    // --- Stage Wh rows (16 x 512, hi/lo) into smem once. Row n = gate*4+uu.
    {
        const __nv_bfloat16* whH = g_wh + (size_t)layer * G * WROW;
        const __nv_bfloat16* whL = g_wl + (size_t)layer * G * WROW;
#pragma unroll
        for (int p = 0; p < 4; p++) {
            const int f = tid + p * NTHR;          // 1024 segs per tile
            const int row = f >> 6, seg = f & 63;
            const int g = row >> 2, uu = row & 3;
            const size_t src = (size_t)(g * 512 + u0 + uu) * WROW + 512 + seg * 8;
            const uint32_t dst = (uint32_t)(row * HPITCH + seg * 8) * 2;
            *(uint4*)(dynsm + WS_H + dst) = *(const uint4*)(whH + src);
            *(uint4*)(dynsm + WS_L + dst) = *(const uint4*)(whL + src);
        }
    }

    // Cell state: thread (b, ul) with b = tid>>2, ul = tid&3.
    const int bT = tid >> 2, ulT = tid & 3;
    float cv = c0l[bT * H + u0 + ulT];
    __syncthreads();

    // ldmatrix lane bases (A mapping proven in gemm_hmma; B uses x4 variant)
    const int sel = lane >> 3, lr = lane & 7;
    const uint32_t aRow = (uint32_t)(wm * 16 + (sel & 1) * 8 + lr);
    const uint32_t aCol = (uint32_t)((sel >> 1) * 8);
    const uint32_t aOffH = sb + HS_H + (aRow * HPITCH + wk * 256 + aCol) * 2;
    const uint32_t aOffL = sb + HS_L + (aRow * HPITCH + wk * 256 + aCol) * 2;
    // B x4: m0=(n lr,k0) m1=(n lr,k8) m2=(n lr+8,k0) m3=(n lr+8,k8)
    const uint32_t bRow = (uint32_t)(lr + (sel >> 1) * 8);
    const uint32_t bCol = (uint32_t)((sel & 1) * 8);
    const uint32_t bOffH = sb + WS_H + (bRow * HPITCH + wk * 256 + bCol) * 2;
    const uint32_t bOffL = sb + WS_L + (bRow * HPITCH + wk * 256 + bCol) * 2;

    // --- R13: load ALL B fragments into registers once (32 LDSM4 at init).
    uint32_t bhr[16][4], blr[16][4];
#pragma unroll
    for (int ks = 0; ks < 16; ks++) {
        LDSM4(bhr[ks][0], bhr[ks][1], bhr[ks][2], bhr[ks][3], bOffH + ks * 32);
        LDSM4(blr[ks][0], blr[ks][1], blr[ks][2], blr[ks][3], bOffL + ks * 32);
    }

    float* xs   = (float*)(dynsm + XS_OFF);
    float* gred = (float*)(dynsm + GR_OFF);

    // Per-warp h-stage bases (each warp stages its own disjoint region)
    const uint32_t stHd = sb + HS_H + ((uint32_t)(wm * 16) * HPITCH + wk * 256) * 2 + lane * 16;
    const uint32_t stLd = sb + HS_L + ((uint32_t)(wm * 16) * HPITCH + wk * 256) * 2 + lane * 16;
    const size_t   stSrc = (size_t)(wm * 16) * 512 + wk * 256 + lane * 8;

    for (int t = 0; t < S; t++) {
        const int rbuf = (t + 1) & 1, wbuf = t & 1;

        // Group 1: h stage (own warp's 16 rows x 256 halves, hi+lo)
        {
            const __nv_bfloat16* srcH = g_hbf[rbuf][0] + stSrc;
            const __nv_bfloat16* srcL = g_hbf[rbuf][1] + stSrc;
#pragma unroll
            for (int i = 0; i < 16; i++) {
                CPASYNC(stHd + (uint32_t)(i * HPITCH) * 2, srcH + (size_t)i * 512);
                CPASYNC(stLd + (uint32_t)(i * HPITCH) * 2, srcL + (size_t)i * 512);
            }
            CPCOMMIT();
        }
        // Group 2 (newest): xg -> xs (DRAM; waited only before elementwise)
        CPASYNC(sb + XS_OFF + (uint32_t)(bT * 16 + ulT * 4) * 4,
                g_xg + (size_t)t * B * G + bT * G + ulT * 512 + u0);
        CPCOMMIT();

        CPWAIT(1);        // wait h group only (xg still pending)
        __syncwarp();

        // 16 k-steps x (AhBh -> main, AhBl + AlBh -> corr); B from registers
        float dm[2][4] = {}, dc[2][4] = {};
#pragma unroll
        for (int ks = 0; ks < 16; ks++) {
            uint32_t ah[4], al[4];
            LDSM4(ah[0], ah[1], ah[2], ah[3], aOffH + ks * 32);
            LDSM4(al[0], al[1], al[2], al[3], aOffL + ks * 32);
            MMA16816(dm[0], ah, bhr[ks]);
            MMA16816(dm[1], ah, bhr[ks] + 2);
            MMA16816(dc[0], ah, blr[ks]);
            MMA16816(dc[1], ah, blr[ks] + 2);
            MMA16816(dc[0], al, bhr[ks]);
            MMA16816(dc[1], al, bhr[ks] + 2);
        }

        // Both k-halves store partials; elementwise adds them.
        {
            const int gq = lane >> 2, tq = lane & 3;
            float* gr = gred + wk * (64 * 18);
#pragma unroll
            for (int j = 0; j < 2; j++) {
                *(float2*)(&gr[(wm * 16 + gq) * 18 + j * 8 + tq * 2]) =
                    make_float2(dm[j][0] + dc[j][0], dm[j][1] + dc[j][1]);
                *(float2*)(&gr[(wm * 16 + gq + 8) * 18 + j * 8 + tq * 2]) =
                    make_float2(dm[j][2] + dc[j][2], dm[j][3] + dc[j][3]);
            }
        }
        __syncthreads();

        // Elementwise update: thread (bT, ulT)
        {
            CPWAIT(0);        // xg group done (long since, behind mma)
            __syncwarp();
            const int u = u0 + ulT;
            const float gi = gred[bT * 18 +  0 + ulT] + gred[64 * 18 + bT * 18 +  0 + ulT]
                           + xs[bT * 16 +  0 + ulT];
            const float gf = gred[bT * 18 +  4 + ulT] + gred[64 * 18 + bT * 18 +  4 + ulT]
                           + xs[bT * 16 +  4 + ulT];
            const float go = gred[bT * 18 +  8 + ulT] + gred[64 * 18 + bT * 18 +  8 + ulT]
                           + xs[bT * 16 +  8 + ulT];
            const float gg = gred[bT * 18 + 12 + ulT] + gred[64 * 18 + bT * 18 + 12 + ulT]
                           + xs[bT * 16 + 12 + ulT];
            const float i_ = __fdividef(1.f, 1.f + __expf(-gi));
            const float f_ = __fdividef(1.f, 1.f + __expf(-gf));
            const float o_ = __fdividef(1.f, 1.f + __expf(-go));
            const float gv = tanhf(gg);
            cv = f_ * cv + i_ * gv;
            const float hnew = o_ * tanhf(cv);

            __nv_bfloat16 hh, hl;
            bsplit(hnew, hh, hl);
            g_hbf[wbuf][0][bT * H + u] = hh;
            g_hbf[wbuf][1][bT * H + u] = hl;

            if (layer == 0) {
                const size_t o = ((size_t)t * B + bT) * 512 + u;
                g_y1h[o] = hh;
                g_y1l[o] = hl;
            } else {
                dout[(size_t)bT * S * H + (size_t)t * H + u] = hnew;
            }
            if (t == S - 1) {
                const size_t BSH = (size_t)B * S * H, BH = (size_t)B * H;
                dout[BSH + (size_t)layer * BH + bT * H + u] = hnew;
                dout[BSH + 2 * BH + (size_t)layer * BH + bT * H + u] = cv;
            }
        }

        // Grid-wide barrier (R9 proven): single counter, release/acquire.
        if (t != S - 1) {
            __syncthreads();
            if (tid == 0) {
                asm volatile("red.release.gpu.add.u32 [%0], %1;"
                             :: "l"(bar), "r"(1u) : "memory");
                const unsigned tgt = (unsigned)(t + 1) * NCTA;
                unsigned v;
                do {
                    asm volatile("ld.acquire.gpu.u32 %0, [%1];"
                                 : "=r"(v) : "l"(bar) : "memory");
                } while (v < tgt);
            }
            __syncthreads();
        }
    }
}

// ---------------------------------------------------------------------------
// Launch: split_x, split_w; per layer: GEMM, init_h, persistent recurrence.
// 8 graph nodes. No allocs, no syncs, graph-capturable.
// ---------------------------------------------------------------------------
extern "C" void kernel_launch(void* const* d_in, const int* in_sizes, int n_in,
                              void* d_out, int out_size)
{
    const float* x  = (const float*)d_in[0];
    const float* W  = (const float*)d_in[1];
    const float* bb = (const float*)d_in[2];
    const float* h0 = (const float*)d_in[3];
    const float* c0 = (const float*)d_in[4];
    float* out = (float*)d_out;

    cudaFuncSetAttribute(gemm_hmma, cudaFuncAttributeMaxDynamicSharedMemorySize, GSMEM);
    cudaFuncSetAttribute(lstm_persist, cudaFuncAttributeMaxDynamicSharedMemorySize, P2_SMEM);

    split_x<<<(M_TOT * 512 / 4) / 256, 256>>>(x);
    split_w<<<(2 * G * WROW / 4) / 256, 256>>>(W);

    for (int layer = 0; layer < 2; layer++) {
        gemm_hmma<<<dim3(16, 512), 256, GSMEM>>>(bb + layer * G, layer);
        init_h<<<(B * H) / 256, 256>>>(h0 + (size_t)layer * B * H);
        lstm_persist<<<NCTA, NTHR, P2_SMEM>>>(layer, c0 + (size_t)layer * B * H, out);
    }
}

// round 16
// speedup vs baseline: 1.2906x; 1.1525x over previous
#include <cuda_runtime.h>
#include <cuda_bf16.h>
#include <math.h>
#include <cstdint>

// Problem constants
#define B    64
#define S    1024
#define D    512
#define H    512
#define G    2048      // 4*H
#define WROW 1024      // D+H, row stride of W
#define M_TOT (S*B)    // 65536 GEMM rows, m = t*B + b
#define NCTA 128
#define NTHR 256

// ---------------------------------------------------------------------------
// Scratch (__device__ globals: sanctioned alloc-free workaround)
// ---------------------------------------------------------------------------
__device__ __nv_bfloat16 g_xh [(size_t)M_TOT * 512];     // layer-0 A hi
__device__ __nv_bfloat16 g_xl [(size_t)M_TOT * 512];     // layer-0 A lo
__device__ __nv_bfloat16 g_y1h[(size_t)M_TOT * 512];     // layer-1 A hi
__device__ __nv_bfloat16 g_y1l[(size_t)M_TOT * 512];     // layer-1 A lo
__device__ __nv_bfloat16 g_wh [2 * (size_t)G * WROW];    // W hi, [layer][n][WROW]
__device__ __nv_bfloat16 g_wl [2 * (size_t)G * WROW];    // W lo
__device__ float g_xg[(size_t)S * B * G];                // input gates (t*B+b, G)
__device__ __nv_bfloat16 g_hbf[2][2][B * H];             // ping-pong h, [buf][hi/lo]
__device__ unsigned g_cnt[2][4 * 32];                    // 4 pair-counters, 128B apart

// ---------------------------------------------------------------------------
// PTX helpers (arch-portable: sm_80+ only)
// ---------------------------------------------------------------------------
__device__ __forceinline__ uint32_t smem_u32(const void* p) {
    uint32_t a;
    asm("{ .reg .u64 t; cvta.to.shared.u64 t, %1; cvt.u32.u64 %0, t; }"
        : "=r"(a) : "l"(p));
    return a;
}

#define CPASYNC(sm, gm) \
    asm volatile("cp.async.cg.shared.global [%0], [%1], 16;" :: "r"(sm), "l"(gm))
#define CPCOMMIT() asm volatile("cp.async.commit_group;" ::: "memory")
#define CPWAIT(n)  asm volatile("cp.async.wait_group %0;" :: "n"(n) : "memory")

#define LDSM4(r0, r1, r2, r3, addr) \
    asm volatile("ldmatrix.sync.aligned.m8n8.x4.shared.b16 {%0,%1,%2,%3}, [%4];" \
        : "=r"(r0), "=r"(r1), "=r"(r2), "=r"(r3) : "r"(addr))
#define LDSM2(r0, r1, addr) \
    asm volatile("ldmatrix.sync.aligned.m8n8.x2.shared.b16 {%0,%1}, [%2];" \
        : "=r"(r0), "=r"(r1) : "r"(addr))

#define MMA16816(d, a, b) \
    asm volatile("mma.sync.aligned.m16n8k16.row.col.f32.bf16.bf16.f32 " \
        "{%0,%1,%2,%3},{%4,%5,%6,%7},{%8,%9},{%0,%1,%2,%3};" \
        : "+f"((d)[0]), "+f"((d)[1]), "+f"((d)[2]), "+f"((d)[3]) \
        : "r"((a)[0]), "r"((a)[1]), "r"((a)[2]), "r"((a)[3]), \
          "r"((b)[0]), "r"((b)[1]))

#define NAMED_BAR(id, cnt_) \
    asm volatile("bar.sync %0, %1;" :: "r"(id), "r"(cnt_) : "memory")

__device__ __forceinline__ void bsplit(float v, __nv_bfloat16& h, __nv_bfloat16& l) {
    h = __float2bfloat16(v);
    l = __float2bfloat16(v - __bfloat162float(h));
}

// ---------------------------------------------------------------------------
// Split kernels: fp32 -> bf16 hi/lo
// ---------------------------------------------------------------------------
__global__ void __launch_bounds__(256) split_x(const float* __restrict__ x)
{
    const size_t i4 = (size_t)blockIdx.x * 256 + threadIdx.x;  // over M_TOT*512/4
    const float4 v = ((const float4*)x)[i4];
    const size_t idx = i4 * 4;                 // (b, t, k) in x layout
    const int k = (int)(idx & 511);
    const int t = (int)((idx >> 9) & 1023);
    const int b = (int)(idx >> 19);
    const size_t o = ((size_t)t * B + b) * 512 + k;   // GEMM A layout (m, k)
    __nv_bfloat16 h0, l0, h1, l1, h2, l2, h3, l3;
    bsplit(v.x, h0, l0); bsplit(v.y, h1, l1);
    bsplit(v.z, h2, l2); bsplit(v.w, h3, l3);
    __nv_bfloat162 a, bb2;
    a.x = h0; a.y = h1; bb2.x = h2; bb2.y = h3;
    *(__nv_bfloat162*)(g_xh + o)     = a;
    *(__nv_bfloat162*)(g_xh + o + 2) = bb2;
    a.x = l0; a.y = l1; bb2.x = l2; bb2.y = l3;
    *(__nv_bfloat162*)(g_xl + o)     = a;
    *(__nv_bfloat162*)(g_xl + o + 2) = bb2;
}

// Full-W split: source layout [layer][n][WROW] is copied linearly.
__global__ void __launch_bounds__(256) split_w(const float* __restrict__ W)
{
    const size_t i4 = (size_t)blockIdx.x * 256 + threadIdx.x;  // over 2*G*WROW/4
    const float4 v = ((const float4*)W)[i4];
    const size_t idx = i4 * 4;
    __nv_bfloat16 h0, l0, h1, l1, h2, l2, h3, l3;
    bsplit(v.x, h0, l0); bsplit(v.y, h1, l1);
    bsplit(v.z, h2, l2); bsplit(v.w, h3, l3);
    __nv_bfloat162 a, bb2;
    a.x = h0; a.y = h1; bb2.x = h2; bb2.y = h3;
    *(__nv_bfloat162*)(g_wh + idx)     = a;
    *(__nv_bfloat162*)(g_wh + idx + 2) = bb2;
    a.x = l0; a.y = l1; bb2.x = l2; bb2.y = l3;
    *(__nv_bfloat162*)(g_wl + idx)     = a;
    *(__nv_bfloat162*)(g_wl + idx + 2) = bb2;
}

// Convert h0 (fp32) into the bf16 ping-pong buffer read at t=0 (index 1).
__global__ void __launch_bounds__(256) init_h(const float* __restrict__ h0l)
{
    const int i = blockIdx.x * 256 + threadIdx.x;   // 0..B*H-1
    __nv_bfloat16 hh, hl;
    bsplit(h0l[i], hh, hl);
    g_hbf[1][0][i] = hh;
    g_hbf[1][1][i] = hl;
}

// ---------------------------------------------------------------------------
// HMMA bf16-split GEMM: xg[m][n] = sum_k A[m][k]*Wx[n][k] + bias[n]
// (unchanged — proven; also zeroes this layer's pair counters)
// ---------------------------------------------------------------------------
#define APITCH 72
#define ATILEB (128 * APITCH * 2)        // 18432 B per operand tile
#define STAGEB (2 * ATILEB)              // A + B per stage
#define GSMEM  (2 * STAGEB)              // double buffered = 73728 B

__global__ void __launch_bounds__(256) gemm_hmma(
    const float* __restrict__ bias, int layer)
{
    if (blockIdx.x == 0 && blockIdx.y == 0 && threadIdx.x < 4)
        g_cnt[layer][threadIdx.x * 32] = 0u;   // reset pair counters

    const __nv_bfloat16* __restrict__ Ah = layer ? g_y1h : g_xh;
    const __nv_bfloat16* __restrict__ Al = layer ? g_y1l : g_xl;
    const __nv_bfloat16* __restrict__ Bh = g_wh + (size_t)layer * G * WROW;
    const __nv_bfloat16* __restrict__ Bl = g_wl + (size_t)layer * G * WROW;
    const __nv_bfloat16* APs[3] = { Ah, Ah, Al };
    const __nv_bfloat16* BPs[3] = { Bh, Bl, Bh };

    extern __shared__ char dynsm[];
    const uint32_t sbase = smem_u32(dynsm);
    const int tid = threadIdx.x, lane = tid & 31, warp = tid >> 5;
    const int wm = warp & 1, wn = warp >> 1;          // warp grid 2(M) x 4(N)
    const int m0 = blockIdx.y * 128, n0 = blockIdx.x * 128;

    const int sel = lane >> 3, lr = lane & 7;
    const uint32_t aRow  = wm * 64 + (sel & 1) * 8 + lr;
    const uint32_t aColB = (sel >> 1) * 8;
    const uint32_t bRow  = wn * 32 + lr;
    const uint32_t bColB = (sel & 1) * 8;

    float d[4][4][4];
#pragma unroll
    for (int i = 0; i < 4; i++)
#pragma unroll
        for (int j = 0; j < 4; j++)
#pragma unroll
            for (int q = 0; q < 4; q++) d[i][j][q] = 0.0f;

    auto issue = [&](int c, int buf) {
        const int term = c >> 3, kg = (c & 7) * 64;
        const __nv_bfloat16* Ap = APs[term];
        const __nv_bfloat16* Bp = BPs[term];
        const uint32_t sA = sbase + buf * STAGEB;
        const uint32_t sB = sA + ATILEB;
#pragma unroll
        for (int p = 0; p < 4; p++) {
            const int f = tid + p * 256;
            const int row = f >> 3, seg = f & 7;
            const uint32_t so = (uint32_t)(row * APITCH + seg * 8) * 2;
            CPASYNC(sA + so, Ap + (size_t)(m0 + row) * 512 + kg + seg * 8);
            CPASYNC(sB + so, Bp + (size_t)(n0 + row) * WROW + kg + seg * 8);
        }
        CPCOMMIT();
    };

    issue(0, 0);
    for (int c = 0; c < 24; c++) {
        const int buf = c & 1;
        if (c + 1 < 24) { issue(c + 1, buf ^ 1); CPWAIT(1); }
        else            { CPWAIT(0); }
        __syncthreads();

        const uint32_t sA = sbase + buf * STAGEB;
        const uint32_t sB = sA + ATILEB;
        const uint32_t aBase = sA + (aRow * APITCH + aColB) * 2;
        const uint32_t bBase = sB + (bRow * APITCH + bColB) * 2;

#pragma unroll
        for (int ks = 0; ks < 4; ks++) {
            uint32_t a[4][4], b[4][2];
#pragma unroll
            for (int i = 0; i < 4; i++)
                LDSM4(a[i][0], a[i][1], a[i][2], a[i][3],
                      aBase + (uint32_t)(i * 16 * APITCH + ks * 16) * 2);
#pragma unroll
            for (int j = 0; j < 4; j++)
                LDSM2(b[j][0], b[j][1],
                      bBase + (uint32_t)(j * 8 * APITCH + ks * 16) * 2);
#pragma unroll
            for (int i = 0; i < 4; i++)
#pragma unroll
                for (int j = 0; j < 4; j++)
                    MMA16816(d[i][j], a[i], b[j]);
        }
        __syncthreads();
    }

    const int gq = lane >> 2, tq = lane & 3;
#pragma unroll
    for (int i = 0; i < 4; i++) {
#pragma unroll
        for (int j = 0; j < 4; j++) {
            const int col = n0 + wn * 32 + j * 8 + tq * 2;
            const int row0 = m0 + wm * 64 + i * 16 + gq;
            const float b0 = bias[col], b1 = bias[col + 1];
            float2 v0, v1;
            v0.x = d[i][j][0] + b0; v0.y = d[i][j][1] + b1;
            v1.x = d[i][j][2] + b0; v1.y = d[i][j][3] + b1;
            *(float2*)(g_xg + (size_t)row0 * G + col) = v0;
            *(float2*)(g_xg + (size_t)(row0 + 8) * G + col) = v1;
        }
    }
}

// ---------------------------------------------------------------------------
// Persistent HMMA recurrence v5 (R13 base + warp-pair specialization):
// 4 independent pair-pipelines per CTA {(wm,0),(wm,1)}. Steady state has NO
// __syncthreads: mma -> 64-thr named barrier -> wk=0 elementwise + h write ->
// per-pair global counter release -> out writes overlap -> acquire-poll.
// hs is warp-private; xs/gred are pair-private; B frags live in registers.
// ---------------------------------------------------------------------------
#define HPITCH 520                       // halves per row: 1040 B
#define HS_H   0
#define HS_L   (HS_H + 64 * HPITCH * 2)      // 66560
#define WS_H   (HS_L + 64 * HPITCH * 2)      // 133120 (init-only staging)
#define WS_L   (WS_H + 16 * HPITCH * 2)      // 149760
#define XS_OFF (WS_L + 16 * HPITCH * 2)      // 166400, [4 pair][16][16] fp32
#define GR_OFF (XS_OFF + 4 * 256 * 4)        // 170496, [4 pair][2][16][18] fp32
#define P2_SMEM (GR_OFF + 4 * 2 * 16 * 18 * 4)   // 179712 B

__global__ void __launch_bounds__(NTHR, 1) lstm_persist(
    int layer,
    const float* __restrict__ c0l,
    float* __restrict__ dout)
{
    extern __shared__ char dynsm[];
    const uint32_t sb = smem_u32(dynsm);
    const int tid = threadIdx.x, lane = tid & 31, warp = tid >> 5;
    const int wm = warp & 3;            // pair id / m-tile: batches [wm*16,+16)
    const int wk = warp >> 2;           // k-half: k in [wk*256, wk*256+256)
    const int u0 = blockIdx.x * 4;
    unsigned* cnt = g_cnt[layer] + wm * 32;    // this pair's counter

    // --- Stage Wh rows (16 x 512, hi/lo) into smem once. Row n = gate*4+uu.
    {
        const __nv_bfloat16* whH = g_wh + (size_t)layer * G * WROW;
        const __nv_bfloat16* whL = g_wl + (size_t)layer * G * WROW;
#pragma unroll
        for (int p = 0; p < 4; p++) {
            const int f = tid + p * NTHR;          // 1024 segs per tile
            const int row = f >> 6, seg = f & 63;
            const int g = row >> 2, uu = row & 3;
            const size_t src = (size_t)(g * 512 + u0 + uu) * WROW + 512 + seg * 8;
            const uint32_t dst = (uint32_t)(row * HPITCH + seg * 8) * 2;
            *(uint4*)(dynsm + WS_H + dst) = *(const uint4*)(whH + src);
            *(uint4*)(dynsm + WS_L + dst) = *(const uint4*)(whL + src);
        }
    }
    __syncthreads();

    // ldmatrix lane bases (A mapping proven; B x4 variant, proven)
    const int sel = lane >> 3, lr = lane & 7;
    const uint32_t aRow = (uint32_t)(wm * 16 + (sel & 1) * 8 + lr);
    const uint32_t aCol = (uint32_t)((sel >> 1) * 8);
    const uint32_t aOffH = sb + HS_H + (aRow * HPITCH + wk * 256 + aCol) * 2;
    const uint32_t aOffL = sb + HS_L + (aRow * HPITCH + wk * 256 + aCol) * 2;
    const uint32_t bRow = (uint32_t)(lr + (sel >> 1) * 8);
    const uint32_t bCol = (uint32_t)((sel & 1) * 8);
    const uint32_t bOffH = sb + WS_H + (bRow * HPITCH + wk * 256 + bCol) * 2;
    const uint32_t bOffL = sb + WS_L + (bRow * HPITCH + wk * 256 + bCol) * 2;

    // B fragments in registers permanently (32 LDSM4 at init).
    uint32_t bhr[16][4], blr[16][4];
#pragma unroll
    for (int ks = 0; ks < 16; ks++) {
        LDSM4(bhr[ks][0], bhr[ks][1], bhr[ks][2], bhr[ks][3], bOffH + ks * 32);
        LDSM4(blr[ks][0], blr[ks][1], blr[ks][2], blr[ks][3], bOffL + ks * 32);
    }

    // Pair-private smem regions
    float* xsP = (float*)(dynsm + XS_OFF) + wm * 256;            // [16][16]
    float* gr0 = (float*)(dynsm + GR_OFF) + (wm * 2 + 0) * 288;  // [16][18]
    float* gr1 = (float*)(dynsm + GR_OFF) + (wm * 2 + 1) * 288;
    float* grW = wk ? gr1 : gr0;

    // xg fetch mapping: j = wk*32 + lane over the pair's 64 (bb, gate) slots
    const int jX = wk * 32 + lane;
    const int bbX = jX >> 2, gX = jX & 3;

    // Cell state: wk==0 lanes own 2 (bb, uu) values: j = lane*2 + e
    float cv[2];
    if (wk == 0) {
#pragma unroll
        for (int e = 0; e < 2; e++) {
            const int j = lane * 2 + e, bb = j >> 2, uu = j & 3;
            cv[e] = c0l[(wm * 16 + bb) * H + u0 + uu];
        }
    }

    // Per-warp h-stage bases (warp-private region of hs)
    const uint32_t stHd = sb + HS_H + ((uint32_t)(wm * 16) * HPITCH + wk * 256) * 2 + lane * 16;
    const uint32_t stLd = sb + HS_L + ((uint32_t)(wm * 16) * HPITCH + wk * 256) * 2 + lane * 16;
    const size_t   stSrc = (size_t)(wm * 16) * 512 + wk * 256 + lane * 8;

    for (int t = 0; t < S; t++) {
        const int rbuf = (t + 1) & 1, wbuf = t & 1;

        // Group 1: h stage (own warp's 16 rows x 256 halves, hi+lo)
        {
            const __nv_bfloat16* srcH = g_hbf[rbuf][0] + stSrc;
            const __nv_bfloat16* srcL = g_hbf[rbuf][1] + stSrc;
#pragma unroll
            for (int i = 0; i < 16; i++) {
                CPASYNC(stHd + (uint32_t)(i * HPITCH) * 2, srcH + (size_t)i * 512);
                CPASYNC(stLd + (uint32_t)(i * HPITCH) * 2, srcL + (size_t)i * 512);
            }
            CPCOMMIT();
        }
        // Group 2 (newest): xg -> xsP (pair slot (bbX, gX))
        CPASYNC(sb + XS_OFF + (uint32_t)(wm * 256 + bbX * 16 + gX * 4) * 4,
                g_xg + (size_t)t * B * G + (wm * 16 + bbX) * G + gX * 512 + u0);
        CPCOMMIT();

        CPWAIT(1);        // h group done (xg still pending)
        __syncwarp();

        // 16 k-steps x (AhBh -> main, AhBl + AlBh -> corr); B from registers
        float dm[2][4] = {}, dc[2][4] = {};
#pragma unroll
        for (int ks = 0; ks < 16; ks++) {
            uint32_t ah[4], al[4];
            LDSM4(ah[0], ah[1], ah[2], ah[3], aOffH + ks * 32);
            LDSM4(al[0], al[1], al[2], al[3], aOffL + ks * 32);
            MMA16816(dm[0], ah, bhr[ks]);
            MMA16816(dm[1], ah, bhr[ks] + 2);
            MMA16816(dc[0], ah, blr[ks]);
            MMA16816(dc[1], ah, blr[ks] + 2);
            MMA16816(dc[0], al, bhr[ks]);
            MMA16816(dc[1], al, bhr[ks] + 2);
        }

        // Store partials to this warp's gred region (pair-local rows)
        {
            const int gq = lane >> 2, tq = lane & 3;
#pragma unroll
            for (int j = 0; j < 2; j++) {
                *(float2*)(&grW[gq * 18 + j * 8 + tq * 2]) =
                    make_float2(dm[j][0] + dc[j][0], dm[j][1] + dc[j][1]);
                *(float2*)(&grW[(gq + 8) * 18 + j * 8 + tq * 2]) =
                    make_float2(dm[j][2] + dc[j][2], dm[j][3] + dc[j][3]);
            }
        }
        CPWAIT(0);                       // xg landed (hidden behind mma)
        NAMED_BAR(wm + 1, 64);           // pair barrier (drains smem stores)

        if (wk == 0) {
            float hnewv[2];
            __nv_bfloat16 hhv[2], hlv[2];
#pragma unroll
            for (int e = 0; e < 2; e++) {
                const int j = lane * 2 + e, bb = j >> 2, uu = j & 3;
                const float gi = gr0[bb * 18 +  0 + uu] + gr1[bb * 18 +  0 + uu]
                               + xsP[bb * 16 +  0 + uu];
                const float gf = gr0[bb * 18 +  4 + uu] + gr1[bb * 18 +  4 + uu]
                               + xsP[bb * 16 +  4 + uu];
                const float go = gr0[bb * 18 +  8 + uu] + gr1[bb * 18 +  8 + uu]
                               + xsP[bb * 16 +  8 + uu];
                const float gg = gr0[bb * 18 + 12 + uu] + gr1[bb * 18 + 12 + uu]
                               + xsP[bb * 16 + 12 + uu];
                const float i_ = __fdividef(1.f, 1.f + __expf(-gi));
                const float f_ = __fdividef(1.f, 1.f + __expf(-gf));
                const float o_ = __fdividef(1.f, 1.f + __expf(-go));
                const float gv = tanhf(gg);
                cv[e] = f_ * cv[e] + i_ * gv;
                hnewv[e] = o_ * tanhf(cv[e]);
                bsplit(hnewv[e], hhv[e], hlv[e]);
                g_hbf[wbuf][0][(wm * 16 + bb) * H + u0 + uu] = hhv[e];
                g_hbf[wbuf][1][(wm * 16 + bb) * H + u0 + uu] = hlv[e];
            }
            if (lane == 0)
                asm volatile("red.release.gpu.add.u32 [%0], %1;"
                             :: "l"(cnt), "r"(1u) : "memory");
            // Output writes AFTER the signal — overlap the barrier wait.
#pragma unroll
            for (int e = 0; e < 2; e++) {
                const int j = lane * 2 + e, bb = j >> 2, uu = j & 3;
                const int b = wm * 16 + bb, u = u0 + uu;
                if (layer == 0) {
                    const size_t o = ((size_t)t * B + b) * 512 + u;
                    g_y1h[o] = hhv[e];
                    g_y1l[o] = hlv[e];
                } else {
                    dout[(size_t)b * S * H + (size_t)t * H + u] = hnewv[e];
                }
                if (t == S - 1) {
                    const size_t BSH = (size_t)B * S * H, BH = (size_t)B * H;
                    dout[BSH + (size_t)layer * BH + b * H + u] = hnewv[e];
                    dout[BSH + 2 * BH + (size_t)layer * BH + b * H + u] = cv[e];
                }
            }
        }

        // Pair-scope grid barrier: wait all 128 CTAs' pair-wm signals.
        if (t != S - 1) {
            const unsigned tgt = (unsigned)(t + 1) * NCTA;
            unsigned v;
            do {
                asm volatile("ld.acquire.gpu.u32 %0, [%1];"
                             : "=r"(v) : "l"(cnt) : "memory");
            } while (v < tgt);
            __syncwarp();
        }
    }
}

// ---------------------------------------------------------------------------
// Launch: split_x, split_w; per layer: GEMM, init_h, persistent recurrence.
// 8 graph nodes. No allocs, no syncs, graph-capturable.
// ---------------------------------------------------------------------------
extern "C" void kernel_launch(void* const* d_in, const int* in_sizes, int n_in,
                              void* d_out, int out_size)
{
    const float* x  = (const float*)d_in[0];
    const float* W  = (const float*)d_in[1];
    const float* bb = (const float*)d_in[2];
    const float* h0 = (const float*)d_in[3];
    const float* c0 = (const float*)d_in[4];
    float* out = (float*)d_out;

    cudaFuncSetAttribute(gemm_hmma, cudaFuncAttributeMaxDynamicSharedMemorySize, GSMEM);
    cudaFuncSetAttribute(lstm_persist, cudaFuncAttributeMaxDynamicSharedMemorySize, P2_SMEM);

    split_x<<<(M_TOT * 512 / 4) / 256, 256>>>(x);
    split_w<<<(2 * G * WROW / 4) / 256, 256>>>(W);

    for (int layer = 0; layer < 2; layer++) {
        gemm_hmma<<<dim3(16, 512), 256, GSMEM>>>(bb + layer * G, layer);
        init_h<<<(B * H) / 256, 256>>>(h0 + (size_t)layer * B * H);
        lstm_persist<<<NCTA, NTHR, P2_SMEM>>>(layer, c0 + (size_t)layer * B * H, out);
    }
}

// round 17
// speedup vs baseline: 1.3984x; 1.0835x over previous
#include <cuda_runtime.h>
#include <cuda_bf16.h>
#include <math.h>
#include <cstdint>

// Problem constants
#define B    64
#define S    1024
#define D    512
#define H    512
#define G    2048      // 4*H
#define WROW 1024      // D+H, row stride of W
#define M_TOT (S*B)    // 65536 GEMM rows, m = t*B + b
#define NCTA 128
#define NTHR 256

// ---------------------------------------------------------------------------
// Scratch (__device__ globals: sanctioned alloc-free workaround)
// ---------------------------------------------------------------------------
__device__ __nv_bfloat16 g_xh [(size_t)M_TOT * 512];     // layer-0 A hi
__device__ __nv_bfloat16 g_xl [(size_t)M_TOT * 512];     // layer-0 A lo
__device__ __nv_bfloat16 g_y1h[(size_t)M_TOT * 512];     // layer-1 A hi
__device__ __nv_bfloat16 g_y1l[(size_t)M_TOT * 512];     // layer-1 A lo
__device__ __nv_bfloat16 g_wh [2 * (size_t)G * WROW];    // W hi, [layer][n][WROW]
__device__ __nv_bfloat16 g_wl [2 * (size_t)G * WROW];    // W lo
__device__ float g_xg[(size_t)S * B * G];                // input gates (t*B+b, G)
__device__ __nv_bfloat16 g_hbf[2][2][B * H];             // ping-pong h, [buf][hi/lo]
__device__ unsigned g_cnt[2][4 * 32];                    // 4 bg-counters, 128B apart

// ---------------------------------------------------------------------------
// PTX helpers (arch-portable: sm_80+ only)
// ---------------------------------------------------------------------------
__device__ __forceinline__ uint32_t smem_u32(const void* p) {
    uint32_t a;
    asm("{ .reg .u64 t; cvta.to.shared.u64 t, %1; cvt.u32.u64 %0, t; }"
        : "=r"(a) : "l"(p));
    return a;
}

#define CPASYNC(sm, gm) \
    asm volatile("cp.async.cg.shared.global [%0], [%1], 16;" :: "r"(sm), "l"(gm))
#define CPCOMMIT() asm volatile("cp.async.commit_group;" ::: "memory")
#define CPWAIT(n)  asm volatile("cp.async.wait_group %0;" :: "n"(n) : "memory")

#define LDSM4(r0, r1, r2, r3, addr) \
    asm volatile("ldmatrix.sync.aligned.m8n8.x4.shared.b16 {%0,%1,%2,%3}, [%4];" \
        : "=r"(r0), "=r"(r1), "=r"(r2), "=r"(r3) : "r"(addr))
#define LDSM2(r0, r1, addr) \
    asm volatile("ldmatrix.sync.aligned.m8n8.x2.shared.b16 {%0,%1}, [%2];" \
        : "=r"(r0), "=r"(r1) : "r"(addr))

#define MMA16816(d, a, b) \
    asm volatile("mma.sync.aligned.m16n8k16.row.col.f32.bf16.bf16.f32 " \
        "{%0,%1,%2,%3},{%4,%5,%6,%7},{%8,%9},{%0,%1,%2,%3};" \
        : "+f"((d)[0]), "+f"((d)[1]), "+f"((d)[2]), "+f"((d)[3]) \
        : "r"((a)[0]), "r"((a)[1]), "r"((a)[2]), "r"((a)[3]), \
          "r"((b)[0]), "r"((b)[1]))

#define NAMED_BAR(id, cnt_) \
    asm volatile("bar.sync %0, %1;" :: "r"(id), "r"(cnt_) : "memory")

__device__ __forceinline__ void bsplit(float v, __nv_bfloat16& h, __nv_bfloat16& l) {
    h = __float2bfloat16(v);
    l = __float2bfloat16(v - __bfloat162float(h));
}

// ---------------------------------------------------------------------------
// Split kernels: fp32 -> bf16 hi/lo
// ---------------------------------------------------------------------------
__global__ void __launch_bounds__(256) split_x(const float* __restrict__ x)
{
    const size_t i4 = (size_t)blockIdx.x * 256 + threadIdx.x;  // over M_TOT*512/4
    const float4 v = ((const float4*)x)[i4];
    const size_t idx = i4 * 4;                 // (b, t, k) in x layout
    const int k = (int)(idx & 511);
    const int t = (int)((idx >> 9) & 1023);
    const int b = (int)(idx >> 19);
    const size_t o = ((size_t)t * B + b) * 512 + k;   // GEMM A layout (m, k)
    __nv_bfloat16 h0, l0, h1, l1, h2, l2, h3, l3;
    bsplit(v.x, h0, l0); bsplit(v.y, h1, l1);
    bsplit(v.z, h2, l2); bsplit(v.w, h3, l3);
    __nv_bfloat162 a, bb2;
    a.x = h0; a.y = h1; bb2.x = h2; bb2.y = h3;
    *(__nv_bfloat162*)(g_xh + o)     = a;
    *(__nv_bfloat162*)(g_xh + o + 2) = bb2;
    a.x = l0; a.y = l1; bb2.x = l2; bb2.y = l3;
    *(__nv_bfloat162*)(g_xl + o)     = a;
    *(__nv_bfloat162*)(g_xl + o + 2) = bb2;
}

// Full-W split: source layout [layer][n][WROW] is copied linearly.
__global__ void __launch_bounds__(256) split_w(const float* __restrict__ W)
{
    const size_t i4 = (size_t)blockIdx.x * 256 + threadIdx.x;  // over 2*G*WROW/4
    const float4 v = ((const float4*)W)[i4];
    const size_t idx = i4 * 4;
    __nv_bfloat16 h0, l0, h1, l1, h2, l2, h3, l3;
    bsplit(v.x, h0, l0); bsplit(v.y, h1, l1);
    bsplit(v.z, h2, l2); bsplit(v.w, h3, l3);
    __nv_bfloat162 a, bb2;
    a.x = h0; a.y = h1; bb2.x = h2; bb2.y = h3;
    *(__nv_bfloat162*)(g_wh + idx)     = a;
    *(__nv_bfloat162*)(g_wh + idx + 2) = bb2;
    a.x = l0; a.y = l1; bb2.x = l2; bb2.y = l3;
    *(__nv_bfloat162*)(g_wl + idx)     = a;
    *(__nv_bfloat162*)(g_wl + idx + 2) = bb2;
}

// Convert h0 (fp32) into the bf16 ping-pong buffer read at t=0 (index 1).
__global__ void __launch_bounds__(256) init_h(const float* __restrict__ h0l)
{
    const int i = blockIdx.x * 256 + threadIdx.x;   // 0..B*H-1
    __nv_bfloat16 hh, hl;
    bsplit(h0l[i], hh, hl);
    g_hbf[1][0][i] = hh;
    g_hbf[1][1][i] = hl;
}

// ---------------------------------------------------------------------------
// HMMA bf16-split GEMM: xg[m][n] = sum_k A[m][k]*Wx[n][k] + bias[n]
// (unchanged — proven; also zeroes this layer's bg counters)
// ---------------------------------------------------------------------------
#define APITCH 72
#define ATILEB (128 * APITCH * 2)        // 18432 B per operand tile
#define STAGEB (2 * ATILEB)              // A + B per stage
#define GSMEM  (2 * STAGEB)              // double buffered = 73728 B

__global__ void __launch_bounds__(256) gemm_hmma(
    const float* __restrict__ bias, int layer)
{
    if (blockIdx.x == 0 && blockIdx.y == 0 && threadIdx.x < 4)
        g_cnt[layer][threadIdx.x * 32] = 0u;   // reset bg counters

    const __nv_bfloat16* __restrict__ Ah = layer ? g_y1h : g_xh;
    const __nv_bfloat16* __restrict__ Al = layer ? g_y1l : g_xl;
    const __nv_bfloat16* __restrict__ Bh = g_wh + (size_t)layer * G * WROW;
    const __nv_bfloat16* __restrict__ Bl = g_wl + (size_t)layer * G * WROW;
    const __nv_bfloat16* APs[3] = { Ah, Ah, Al };
    const __nv_bfloat16* BPs[3] = { Bh, Bl, Bh };

    extern __shared__ char dynsm[];
    const uint32_t sbase = smem_u32(dynsm);
    const int tid = threadIdx.x, lane = tid & 31, warp = tid >> 5;
    const int wm = warp & 1, wn = warp >> 1;          // warp grid 2(M) x 4(N)
    const int m0 = blockIdx.y * 128, n0 = blockIdx.x * 128;

    const int sel = lane >> 3, lr = lane & 7;
    const uint32_t aRow  = wm * 64 + (sel & 1) * 8 + lr;
    const uint32_t aColB = (sel >> 1) * 8;
    const uint32_t bRow  = wn * 32 + lr;
    const uint32_t bColB = (sel & 1) * 8;

    float d[4][4][4];
#pragma unroll
    for (int i = 0; i < 4; i++)
#pragma unroll
        for (int j = 0; j < 4; j++)
#pragma unroll
            for (int q = 0; q < 4; q++) d[i][j][q] = 0.0f;

    auto issue = [&](int c, int buf) {
        const int term = c >> 3, kg = (c & 7) * 64;
        const __nv_bfloat16* Ap = APs[term];
        const __nv_bfloat16* Bp = BPs[term];
        const uint32_t sA = sbase + buf * STAGEB;
        const uint32_t sB = sA + ATILEB;
#pragma unroll
        for (int p = 0; p < 4; p++) {
            const int f = tid + p * 256;
            const int row = f >> 3, seg = f & 7;
            const uint32_t so = (uint32_t)(row * APITCH + seg * 8) * 2;
            CPASYNC(sA + so, Ap + (size_t)(m0 + row) * 512 + kg + seg * 8);
            CPASYNC(sB + so, Bp + (size_t)(n0 + row) * WROW + kg + seg * 8);
        }
        CPCOMMIT();
    };

    issue(0, 0);
    for (int c = 0; c < 24; c++) {
        const int buf = c & 1;
        if (c + 1 < 24) { issue(c + 1, buf ^ 1); CPWAIT(1); }
        else            { CPWAIT(0); }
        __syncthreads();

        const uint32_t sA = sbase + buf * STAGEB;
        const uint32_t sB = sA + ATILEB;
        const uint32_t aBase = sA + (aRow * APITCH + aColB) * 2;
        const uint32_t bBase = sB + (bRow * APITCH + bColB) * 2;

#pragma unroll
        for (int ks = 0; ks < 4; ks++) {
            uint32_t a[4][4], b[4][2];
#pragma unroll
            for (int i = 0; i < 4; i++)
                LDSM4(a[i][0], a[i][1], a[i][2], a[i][3],
                      aBase + (uint32_t)(i * 16 * APITCH + ks * 16) * 2);
#pragma unroll
            for (int j = 0; j < 4; j++)
                LDSM2(b[j][0], b[j][1],
                      bBase + (uint32_t)(j * 8 * APITCH + ks * 16) * 2);
#pragma unroll
            for (int i = 0; i < 4; i++)
#pragma unroll
                for (int j = 0; j < 4; j++)
                    MMA16816(d[i][j], a[i], b[j]);
        }
        __syncthreads();
    }

    const int gq = lane >> 2, tq = lane & 3;
#pragma unroll
    for (int i = 0; i < 4; i++) {
#pragma unroll
        for (int j = 0; j < 4; j++) {
            const int col = n0 + wn * 32 + j * 8 + tq * 2;
            const int row0 = m0 + wm * 64 + i * 16 + gq;
            const float b0 = bias[col], b1 = bias[col + 1];
            float2 v0, v1;
            v0.x = d[i][j][0] + b0; v0.y = d[i][j][1] + b1;
            v1.x = d[i][j][2] + b0; v1.y = d[i][j][3] + b1;
            *(float2*)(g_xg + (size_t)row0 * G + col) = v0;
            *(float2*)(g_xg + (size_t)(row0 + 8) * G + col) = v1;
        }
    }
}

// ---------------------------------------------------------------------------
// Persistent HMMA recurrence v6 (batch-tiled):
// CTA = 16 batches (bg) x 16 units (ug). h stage per CTA = ONLY its 16 batch
// rows (4 MB/step chip-wide vs 16 MB before), staged cooperatively. Pair wn
// owns 4 units x 4 gates (identical warp-level structure to v5: A 16xk-half,
// B 16 rows in registers, same mma/gred/elementwise shapes). Barrier: per-
// batch-group counter cnt[bg] (32 CTAs x 4 pairs = 128 signals = NCTA/step).
// ---------------------------------------------------------------------------
#define HPITCH 520                       // halves per row: 1040 B
#define HS_H   0
#define HS_L   (16 * HPITCH * 2)             // 16640
#define WS_H   (2 * 16 * HPITCH * 2)         // 33280 (init-only staging, 64 rows)
#define WS_L   (WS_H + 64 * HPITCH * 2)      // 99840
#define XS_OFF (WS_L + 64 * HPITCH * 2)      // 166400, [4 pair][16][16] fp32
#define GR_OFF (XS_OFF + 4 * 256 * 4)        // 170496, [4 pair][2][16][18] fp32
#define P2_SMEM (GR_OFF + 4 * 2 * 16 * 18 * 4)   // 179712 B

__global__ void __launch_bounds__(NTHR, 1) lstm_persist(
    int layer,
    const float* __restrict__ c0l,
    float* __restrict__ dout)
{
    extern __shared__ char dynsm[];
    const uint32_t sb = smem_u32(dynsm);
    const int tid = threadIdx.x, lane = tid & 31, warp = tid >> 5;
    const int wn = warp & 3;            // pair id: units [ug*16+wn*4, +4)
    const int wk = warp >> 2;           // k-half: k in [wk*256, wk*256+256)
    const int bg = blockIdx.x >> 5;     // batch group: batches [bg*16, +16)
    const int ug = blockIdx.x & 31;     // unit group: units [ug*16, +16)
    const int b0 = bg * 16;
    const int uBase = ug * 16 + wn * 4; // this pair's first unit
    unsigned* cnt = g_cnt[layer] + bg * 32;    // this batch group's counter

    // --- Stage 64 Wh rows (16 units x 4 gates, hi/lo) into smem once.
    // WS row r: wn_=r>>4, gate=(r&15)>>2, uuL=r&3 -> Wh row gate*H+ug*16+wn_*4+uuL
    {
        const __nv_bfloat16* whH = g_wh + (size_t)layer * G * WROW;
        const __nv_bfloat16* whL = g_wl + (size_t)layer * G * WROW;
#pragma unroll
        for (int p = 0; p < 16; p++) {
            const int f = tid + p * NTHR;          // 4096 segs per tile
            const int row = f >> 6, seg = f & 63;
            const int wn_ = row >> 4, rr = row & 15;
            const int g = rr >> 2, uuL = rr & 3;
            const size_t src = (size_t)(g * 512 + ug * 16 + wn_ * 4 + uuL) * WROW
                             + 512 + seg * 8;
            const uint32_t dst = (uint32_t)(row * HPITCH + seg * 8) * 2;
            *(uint4*)(dynsm + WS_H + dst) = *(const uint4*)(whH + src);
            *(uint4*)(dynsm + WS_L + dst) = *(const uint4*)(whL + src);
        }
    }
    __syncthreads();

    // ldmatrix lane bases (A/B x4 maps proven in prior rounds)
    const int sel = lane >> 3, lr = lane & 7;
    const uint32_t aRow = (uint32_t)((sel & 1) * 8 + lr);       // local 0..15
    const uint32_t aCol = (uint32_t)((sel >> 1) * 8);
    const uint32_t aOffH = sb + HS_H + (aRow * HPITCH + wk * 256 + aCol) * 2;
    const uint32_t aOffL = sb + HS_L + (aRow * HPITCH + wk * 256 + aCol) * 2;
    const uint32_t bRow = (uint32_t)(wn * 16 + lr + (sel >> 1) * 8);
    const uint32_t bCol = (uint32_t)((sel & 1) * 8);
    const uint32_t bOffH = sb + WS_H + (bRow * HPITCH + wk * 256 + bCol) * 2;
    const uint32_t bOffL = sb + WS_L + (bRow * HPITCH + wk * 256 + bCol) * 2;

    // B fragments in registers permanently (32 LDSM4 at init).
    uint32_t bhr[16][4], blr[16][4];
#pragma unroll
    for (int ks = 0; ks < 16; ks++) {
        LDSM4(bhr[ks][0], bhr[ks][1], bhr[ks][2], bhr[ks][3], bOffH + ks * 32);
        LDSM4(blr[ks][0], blr[ks][1], blr[ks][2], blr[ks][3], bOffL + ks * 32);
    }

    // Pair-private smem regions
    float* xsP = (float*)(dynsm + XS_OFF) + wn * 256;            // [16][16]
    float* gr0 = (float*)(dynsm + GR_OFF) + (wn * 2 + 0) * 288;  // [16][18]
    float* gr1 = (float*)(dynsm + GR_OFF) + (wn * 2 + 1) * 288;
    float* grW = wk ? gr1 : gr0;

    // xg fetch mapping: j = wk*32 + lane over the pair's 64 (bb, gate) slots
    const int jX = wk * 32 + lane;
    const int bbX = jX >> 2, gX = jX & 3;

    // Cell state: wk==0 lanes own 2 (bb, uu) values: j = lane*2 + e
    float cv[2];
    if (wk == 0) {
#pragma unroll
        for (int e = 0; e < 2; e++) {
            const int j = lane * 2 + e, bb = j >> 2, uu = j & 3;
            cv[e] = c0l[(b0 + bb) * H + uBase + uu];
        }
    }

    for (int t = 0; t < S; t++) {
        const int rbuf = (t + 1) & 1, wbuf = t & 1;

        // Group 1: cooperative h stage (16 rows x 512, hi+lo; 8/thread)
        {
            const __nv_bfloat16* srcH = g_hbf[rbuf][0];
            const __nv_bfloat16* srcL = g_hbf[rbuf][1];
#pragma unroll
            for (int p = 0; p < 4; p++) {
                const int f = tid + p * NTHR;      // 1024 segs
                const int row = f >> 6, seg = f & 63;
                const uint32_t dst = (uint32_t)(row * HPITCH + seg * 8) * 2;
                const size_t src = (size_t)(b0 + row) * 512 + seg * 8;
                CPASYNC(sb + HS_H + dst, srcH + src);
                CPASYNC(sb + HS_L + dst, srcL + src);
            }
            CPCOMMIT();
        }
        // Group 2 (newest): xg -> xsP slot (bbX, gX): cols gX*512 + uBase..+4
        CPASYNC(sb + XS_OFF + (uint32_t)(wn * 256 + bbX * 16 + gX * 4) * 4,
                g_xg + (size_t)t * B * G + (size_t)(b0 + bbX) * G
                     + gX * 512 + ug * 16 + wn * 4);
        CPCOMMIT();

        CPWAIT(1);        // h group done (xg still pending)
        __syncthreads();  // staged tile visible to all warps

        // 16 k-steps x (AhBh -> main, AhBl + AlBh -> corr); B from registers
        float dm[2][4] = {}, dc[2][4] = {};
#pragma unroll
        for (int ks = 0; ks < 16; ks++) {
            uint32_t ah[4], al[4];
            LDSM4(ah[0], ah[1], ah[2], ah[3], aOffH + ks * 32);
            LDSM4(al[0], al[1], al[2], al[3], aOffL + ks * 32);
            MMA16816(dm[0], ah, bhr[ks]);
            MMA16816(dm[1], ah, bhr[ks] + 2);
            MMA16816(dc[0], ah, blr[ks]);
            MMA16816(dc[1], ah, blr[ks] + 2);
            MMA16816(dc[0], al, bhr[ks]);
            MMA16816(dc[1], al, bhr[ks] + 2);
        }

        // Store partials to this warp's gred region (pair-local rows)
        {
            const int gq = lane >> 2, tq = lane & 3;
#pragma unroll
            for (int j = 0; j < 2; j++) {
                *(float2*)(&grW[gq * 18 + j * 8 + tq * 2]) =
                    make_float2(dm[j][0] + dc[j][0], dm[j][1] + dc[j][1]);
                *(float2*)(&grW[(gq + 8) * 18 + j * 8 + tq * 2]) =
                    make_float2(dm[j][2] + dc[j][2], dm[j][3] + dc[j][3]);
            }
        }
        CPWAIT(0);                       // xg landed (hidden behind mma)
        NAMED_BAR(wn + 1, 64);           // pair barrier (drains smem stores)

        if (wk == 0) {
            float hnewv[2];
            __nv_bfloat16 hhv[2], hlv[2];
#pragma unroll
            for (int e = 0; e < 2; e++) {
                const int j = lane * 2 + e, bb = j >> 2, uu = j & 3;
                const float gi = gr0[bb * 18 +  0 + uu] + gr1[bb * 18 +  0 + uu]
                               + xsP[bb * 16 +  0 + uu];
                const float gf = gr0[bb * 18 +  4 + uu] + gr1[bb * 18 +  4 + uu]
                               + xsP[bb * 16 +  4 + uu];
                const float go = gr0[bb * 18 +  8 + uu] + gr1[bb * 18 +  8 + uu]
                               + xsP[bb * 16 +  8 + uu];
                const float gg = gr0[bb * 18 + 12 + uu] + gr1[bb * 18 + 12 + uu]
                               + xsP[bb * 16 + 12 + uu];
                const float i_ = __fdividef(1.f, 1.f + __expf(-gi));
                const float f_ = __fdividef(1.f, 1.f + __expf(-gf));
                const float o_ = __fdividef(1.f, 1.f + __expf(-go));
                const float gv = tanhf(gg);
                cv[e] = f_ * cv[e] + i_ * gv;
                hnewv[e] = o_ * tanhf(cv[e]);
                bsplit(hnewv[e], hhv[e], hlv[e]);
                g_hbf[wbuf][0][(b0 + bb) * H + uBase + uu] = hhv[e];
                g_hbf[wbuf][1][(b0 + bb) * H + uBase + uu] = hlv[e];
            }
            if (lane == 0)
                asm volatile("red.release.gpu.add.u32 [%0], %1;"
                             :: "l"(cnt), "r"(1u) : "memory");
            // Output writes AFTER the signal — overlap the barrier wait.
#pragma unroll
            for (int e = 0; e < 2; e++) {
                const int j = lane * 2 + e, bb = j >> 2, uu = j & 3;
                const int b = b0 + bb, u = uBase + uu;
                if (layer == 0) {
                    const size_t o = ((size_t)t * B + b) * 512 + u;
                    g_y1h[o] = hhv[e];
                    g_y1l[o] = hlv[e];
                } else {
                    dout[(size_t)b * S * H + (size_t)t * H + u] = hnewv[e];
                }
                if (t == S - 1) {
                    const size_t BSH = (size_t)B * S * H, BH = (size_t)B * H;
                    dout[BSH + (size_t)layer * BH + b * H + u] = hnewv[e];
                    dout[BSH + 2 * BH + (size_t)layer * BH + b * H + u] = cv[e];
                }
            }
        }

        // Grid barrier on this batch group: 32 CTAs x 4 pairs = 128 signals.
        if (t != S - 1) {
            if (tid == 0) {
                const unsigned tgt = (unsigned)(t + 1) * NCTA;
                unsigned v;
                do {
                    asm volatile("ld.acquire.gpu.u32 %0, [%1];"
                                 : "=r"(v) : "l"(cnt) : "memory");
                } while (v < tgt);
            }
            __syncthreads();
        }
    }
}

// ---------------------------------------------------------------------------
// Launch: split_x, split_w; per layer: GEMM, init_h, persistent recurrence.
// 8 graph nodes. No allocs, no syncs, graph-capturable.
// ---------------------------------------------------------------------------
extern "C" void kernel_launch(void* const* d_in, const int* in_sizes, int n_in,
                              void* d_out, int out_size)
{
    const float* x  = (const float*)d_in[0];
    const float* W  = (const float*)d_in[1];
    const float* bb = (const float*)d_in[2];
    const float* h0 = (const float*)d_in[3];
    const float* c0 = (const float*)d_in[4];
    float* out = (float*)d_out;

    cudaFuncSetAttribute(gemm_hmma, cudaFuncAttributeMaxDynamicSharedMemorySize, GSMEM);
    cudaFuncSetAttribute(lstm_persist, cudaFuncAttributeMaxDynamicSharedMemorySize, P2_SMEM);

    split_x<<<(M_TOT * 512 / 4) / 256, 256>>>(x);
    split_w<<<(2 * G * WROW / 4) / 256, 256>>>(W);

    for (int layer = 0; layer < 2; layer++) {
        gemm_hmma<<<dim3(16, 512), 256, GSMEM>>>(bb + layer * G, layer);
        init_h<<<(B * H) / 256, 256>>>(h0 + (size_t)layer * B * H);
        lstm_persist<<<NCTA, NTHR, P2_SMEM>>>(layer, c0 + (size_t)layer * B * H, out);
    }
}